// round 9
// baseline (speedup 1.0000x reference)
#include <cuda_runtime.h>
#include <cuda_bf16.h>
#include <math.h>
#include <stdint.h>

#define B_ 2
#define T_ 2048
#define C_ 768
#define H_ 12
#define D_ 64
#define M_ (B_*T_)       // 4096
#define NQKV_ (3*C_)     // 2304
#define K3_ (3*C_)       // expanded K = 2304
#define NSLAB_ (K3_/32)  // 72

// ---------------------------------------------------------------------------
// Scratch (allocation-free rule: __device__ globals).
// IMPORTANT: referenced ONLY from device code — never passed as host-side
// kernel arguments (host shadow symbol != device address; ATS made the R6/R7
// zero-read bug silent).
// ---------------------------------------------------------------------------
__device__ float g_q[B_*H_*T_*D_];
__device__ float g_k[B_*H_*T_*D_];
__device__ float g_v[B_*H_*T_*D_];
__device__ __align__(256) __nv_bfloat16 g_x2[M_*K3_];      // x expanded [M][3K]: hi|hi|lo
__device__ __align__(256) __nv_bfloat16 g_a2[M_*K3_];      // attn out expanded
__device__ __align__(256) __nv_bfloat16 g_w2q[NQKV_*K3_];  // Wqkv^T expanded [N][3K]: hi|lo|hi
__device__ __align__(256) __nv_bfloat16 g_w2o[C_*K3_];     // Wout^T expanded

// ---------------------------------------------------------------------------
// Prep 1: x fp32 [M][C] -> g_x2 bf16 [M][3C] = [hi | hi | lo]
// ---------------------------------------------------------------------------
__global__ void split_expand_kernel(const float* __restrict__ src, int n4) {
    int i = blockIdx.x * blockDim.x + threadIdx.x;
    if (i >= n4) return;
    float4 v = ((const float4*)src)[i];
    float vv[4] = {v.x, v.y, v.z, v.w};
    int idx = i * 4;
    int m = idx / C_, k = idx % C_;
    size_t base = (size_t)m * K3_ + k;
#pragma unroll
    for (int j = 0; j < 4; j++) {
        __nv_bfloat16 hi = __float2bfloat16(vv[j]);
        __nv_bfloat16 lo = __float2bfloat16(vv[j] - __bfloat162float(hi));
        g_x2[base + j]          = hi;
        g_x2[base + C_ + j]     = hi;
        g_x2[base + 2*C_ + j]   = lo;
    }
}

// ---------------------------------------------------------------------------
// Prep 2: W fp32 [K][N] -> Wt bf16 [N][3K] = [hi | lo | hi]
// WHICH 0: Wqkv (N=2304) -> g_w2q.  WHICH 1: Wout (N=768) -> g_w2o.
// ---------------------------------------------------------------------------
template<int WHICH>
__global__ void transpose_split_expand_kernel(const float* __restrict__ W) {
    const int K = C_;
    const int N = (WHICH == 0) ? NQKV_ : C_;
    __nv_bfloat16* Bt = (WHICH == 0) ? g_w2q : g_w2o;

    __shared__ float tile[32][33];
    const int c0 = blockIdx.x * 32;   // N offset
    const int r0 = blockIdx.y * 32;   // K offset
    const int tx = threadIdx.x, ty = threadIdx.y;
#pragma unroll
    for (int i = 0; i < 4; i++)
        tile[ty + i*8][tx] = W[(size_t)(r0 + ty + i*8) * N + c0 + tx];
    __syncthreads();
#pragma unroll
    for (int i = 0; i < 4; i++) {
        float v = tile[tx][ty + i*8];
        __nv_bfloat16 hi = __float2bfloat16(v);
        __nv_bfloat16 lo = __float2bfloat16(v - __bfloat162float(hi));
        int n = c0 + ty + i*8, k = r0 + tx;
        size_t base = (size_t)n * K3_;
        Bt[base + k]        = hi;
        Bt[base + K + k]    = lo;
        Bt[base + 2*K + k]  = hi;
    }
}

// ---------------------------------------------------------------------------
// HMMA GEMM: D[M,N] = A'[M,K3] * B'[N,K3]^T  (split-bf16, fp32 accum)
// 128x128 CTA tile, 8 warps (2x4), warp tile 64x32, K-slab 32.
// Register-prefetch double buffering; explicit LDS fragment gathers per the
// PTX m16n8k16 layout.  smem: A 128x80B + B 128x80B = 20480 B (static).
// MODE 0: A=g_x2, B=g_w2q, scatter to g_q/g_k/g_v.
// MODE 1: A=g_a2, B=g_w2o, write outp [M,C_] fp32.
// ---------------------------------------------------------------------------
template<int MODE>
__global__ __launch_bounds__(256) void mma_gemm_kernel(float* __restrict__ outp)
{
    const __nv_bfloat16* __restrict__ A2 = (MODE == 0) ? g_x2 : g_a2;
    const __nv_bfloat16* __restrict__ B2 = (MODE == 0) ? g_w2q : g_w2o;

    __shared__ __align__(16) unsigned char smem[20480];  // A @0, B @10240

    const int tid = threadIdx.x;
    const int wid = tid >> 5, lane = tid & 31;
    const int gid = lane >> 2, tig = lane & 3;
    const int m0 = blockIdx.y << 7, n0 = blockIdx.x << 7;
    const int warp_m = wid & 1, warp_n = wid >> 1;

    // per-thread load coords: 2 x 16B chunks per matrix (512 chunks over 256 thr)
    const int lr0 = tid >> 2;          // rows 0..63
    const int lr1 = lr0 + 64;          // rows 64..127
    const int lc  = (tid & 3) * 8;     // k-element offset within slab

    const __nv_bfloat16* Abase  = A2 + (size_t)(m0 + lr0) * K3_ + lc;
    const __nv_bfloat16* Abase1 = A2 + (size_t)(m0 + lr1) * K3_ + lc;
    const __nv_bfloat16* Bbase  = B2 + (size_t)(n0 + lr0) * K3_ + lc;
    const __nv_bfloat16* Bbase1 = B2 + (size_t)(n0 + lr1) * K3_ + lc;

    float acc[4][4][4];
#pragma unroll
    for (int a = 0; a < 4; a++)
#pragma unroll
        for (int b = 0; b < 4; b++)
#pragma unroll
            for (int c = 0; c < 4; c++) acc[a][b][c] = 0.f;

    // prefetch slab 0
    uint4 pa0 = *(const uint4*)(Abase);
    uint4 pa1 = *(const uint4*)(Abase1);
    uint4 pb0 = *(const uint4*)(Bbase);
    uint4 pb1 = *(const uint4*)(Bbase1);

    for (int ks = 0; ks < NSLAB_; ks++) {
        // store current slab to smem
        *(uint4*)&smem[lr0*80 + (tid & 3)*16]          = pa0;
        *(uint4*)&smem[lr1*80 + (tid & 3)*16]          = pa1;
        *(uint4*)&smem[10240 + lr0*80 + (tid & 3)*16]  = pb0;
        *(uint4*)&smem[10240 + lr1*80 + (tid & 3)*16]  = pb1;
        __syncthreads();

        // prefetch next slab into registers (overlaps with MMA below)
        if (ks + 1 < NSLAB_) {
            const int ko = (ks + 1) * 32;
            pa0 = *(const uint4*)(Abase + ko);
            pa1 = *(const uint4*)(Abase1 + ko);
            pb0 = *(const uint4*)(Bbase + ko);
            pb1 = *(const uint4*)(Bbase1 + ko);
        }

#pragma unroll
        for (int kst = 0; kst < 2; kst++) {
            // A fragments per PTX m16n8k16 layout
            uint32_t af[4][4];
#pragma unroll
            for (int tm = 0; tm < 4; tm++) {
                const int row = warp_m*64 + tm*16 + gid;
                const unsigned char* pa = &smem[row*80 + kst*32 + tig*4];
                af[tm][0] = *(const uint32_t*)(pa);            // rows 0-7,  k 0-7
                af[tm][1] = *(const uint32_t*)(pa + 8*80);     // rows 8-15, k 0-7
                af[tm][2] = *(const uint32_t*)(pa + 16);       // rows 0-7,  k 8-15
                af[tm][3] = *(const uint32_t*)(pa + 8*80+16);  // rows 8-15, k 8-15
            }
            // B fragments: b0 (k 0-7), b1 (k 8-15) at n = sub-block + gid
            uint32_t bfr[2][2][2];
#pragma unroll
            for (int tp = 0; tp < 2; tp++)
#pragma unroll
                for (int hh = 0; hh < 2; hh++) {
                    const int n = warp_n*32 + tp*16 + hh*8 + gid;
                    const unsigned char* pb = &smem[10240 + n*80 + kst*32 + tig*4];
                    bfr[tp][hh][0] = *(const uint32_t*)(pb);
                    bfr[tp][hh][1] = *(const uint32_t*)(pb + 16);
                }
#pragma unroll
            for (int tm = 0; tm < 4; tm++)
#pragma unroll
                for (int tn = 0; tn < 4; tn++) {
                    asm volatile(
                        "mma.sync.aligned.m16n8k16.row.col.f32.bf16.bf16.f32 "
                        "{%0,%1,%2,%3}, {%4,%5,%6,%7}, {%8,%9}, {%0,%1,%2,%3};"
                        : "+f"(acc[tm][tn][0]), "+f"(acc[tm][tn][1]),
                          "+f"(acc[tm][tn][2]), "+f"(acc[tm][tn][3])
                        : "r"(af[tm][0]), "r"(af[tm][1]), "r"(af[tm][2]), "r"(af[tm][3]),
                          "r"(bfr[tn>>1][tn&1][0]), "r"(bfr[tn>>1][tn&1][1]));
                }
        }
        __syncthreads();
    }

    // ---- epilogue: direct register -> GMEM ----
#pragma unroll
    for (int tm = 0; tm < 4; tm++) {
        const int r0_ = m0 + warp_m*64 + tm*16 + gid;
#pragma unroll
        for (int tn = 0; tn < 4; tn++) {
            const int col = n0 + warp_n*32 + tn*8 + tig*2;
            if (MODE == 1) {
                float2 v0 = {acc[tm][tn][0], acc[tm][tn][1]};
                float2 v1 = {acc[tm][tn][2], acc[tm][tn][3]};
                *(float2*)&outp[(size_t)r0_ * C_ + col]       = v0;
                *(float2*)&outp[(size_t)(r0_ + 8) * C_ + col] = v1;
            } else {
                const int seg = n0 / C_;            // whole CTA in one of q/k/v
                float* dst = (seg == 0) ? g_q : (seg == 1) ? g_k : g_v;
                const int nrel = col - seg * C_;
                const int h = nrel >> 6, d = nrel & 63;
#pragma unroll
                for (int half = 0; half < 2; half++) {
                    const int m = r0_ + half * 8;
                    const int bb = m >> 11, tt = m & (T_ - 1);
                    float2 v = {acc[tm][tn][half*2], acc[tm][tn][half*2 + 1]};
                    *(float2*)&dst[((size_t)(bb*H_ + h)*T_ + tt)*D_ + d] = v;
                }
            }
        }
    }
}

// ---------------------------------------------------------------------------
// Causal flash attention, Br=Bc=64, fp32, online softmax (R1 core, passed).
// Epilogue writes expanded split-bf16 [M][3C] = [hi | hi | lo] into g_a2.
// ---------------------------------------------------------------------------
__global__ __launch_bounds__(256) void attn_kernel() {
    extern __shared__ float sm[];
    float* Qt = sm;
    float* Kt = Qt + 64*65;
    float* Pt = Kt + 64*65;
    float* Vs = Pt + 64*65;

    const int tid = threadIdx.x;
    const int tx = tid & 15, ty = tid >> 4;
    const int bh = blockIdx.y;
    const int b = bh / H_, h = bh % H_;
    const int qt = (gridDim.x - 1) - blockIdx.x;

    const float* qb  = g_q + ((b*H_ + h)*T_ + qt*64) * D_;
    const float* kb0 = g_k + ((b*H_ + h)*T_) * D_;
    const float* vb0 = g_v + ((b*H_ + h)*T_) * D_;

    for (int it = tid; it < 64*16; it += 256) {
        int r = it >> 4, dq = (it & 15) << 2;
        float4 v4 = *(const float4*)&qb[r*64 + dq];
        Qt[(dq+0)*65 + r] = v4.x;
        Qt[(dq+1)*65 + r] = v4.y;
        Qt[(dq+2)*65 + r] = v4.z;
        Qt[(dq+3)*65 + r] = v4.w;
    }

    float m_r[4], l_r[4], o[4][4];
#pragma unroll
    for (int i = 0; i < 4; i++) {
        m_r[i] = -INFINITY; l_r[i] = 0.f;
#pragma unroll
        for (int j = 0; j < 4; j++) o[i][j] = 0.f;
    }
    const float scale = 0.125f;

    for (int kt = 0; kt <= qt; kt++) {
        __syncthreads();
        const float* kb = kb0 + kt*64*D_;
        const float* vb = vb0 + kt*64*D_;
        for (int it = tid; it < 64*16; it += 256) {
            int r = it >> 4, dq = (it & 15) << 2;
            float4 v4 = *(const float4*)&kb[r*64 + dq];
            Kt[(dq+0)*65 + r] = v4.x;
            Kt[(dq+1)*65 + r] = v4.y;
            Kt[(dq+2)*65 + r] = v4.z;
            Kt[(dq+3)*65 + r] = v4.w;
            *(float4*)&Vs[r*64 + dq] = *(const float4*)&vb[r*64 + dq];
        }
        __syncthreads();

        float s[4][4] = {};
#pragma unroll 4
        for (int d = 0; d < 64; d++) {
            float qv[4], kv[4];
#pragma unroll
            for (int i = 0; i < 4; i++) qv[i] = Qt[d*65 + ty*4 + i];
#pragma unroll
            for (int j = 0; j < 4; j++) kv[j] = Kt[d*65 + tx*4 + j];
#pragma unroll
            for (int i = 0; i < 4; i++)
#pragma unroll
                for (int j = 0; j < 4; j++)
                    s[i][j] = fmaf(qv[i], kv[j], s[i][j]);
        }

        if (kt == qt) {
#pragma unroll
            for (int i = 0; i < 4; i++) {
                int r = ty*4 + i;
#pragma unroll
                for (int j = 0; j < 4; j++) {
                    int c = tx*4 + j;
                    s[i][j] = (c <= r) ? s[i][j]*scale : -INFINITY;
                }
            }
        } else {
#pragma unroll
            for (int i = 0; i < 4; i++)
#pragma unroll
                for (int j = 0; j < 4; j++) s[i][j] *= scale;
        }

#pragma unroll
        for (int i = 0; i < 4; i++) {
            float rmax = fmaxf(fmaxf(s[i][0], s[i][1]), fmaxf(s[i][2], s[i][3]));
#pragma unroll
            for (int off = 8; off >= 1; off >>= 1)
                rmax = fmaxf(rmax, __shfl_xor_sync(0xffffffffu, rmax, off));
            float mnew = fmaxf(m_r[i], rmax);
            float corr = __expf(m_r[i] - mnew);
            float p[4], psum = 0.f;
#pragma unroll
            for (int j = 0; j < 4; j++) { p[j] = __expf(s[i][j] - mnew); psum += p[j]; }
#pragma unroll
            for (int off = 8; off >= 1; off >>= 1)
                psum += __shfl_xor_sync(0xffffffffu, psum, off);
            l_r[i] = l_r[i] * corr + psum;
            m_r[i] = mnew;
#pragma unroll
            for (int j = 0; j < 4; j++) o[i][j] *= corr;
#pragma unroll
            for (int j = 0; j < 4; j++)
                Pt[(tx*4 + j)*65 + ty*4 + i] = p[j];
        }
        __syncthreads();

#pragma unroll 4
        for (int jx = 0; jx < 64; jx++) {
            float pv[4];
#pragma unroll
            for (int i = 0; i < 4; i++) pv[i] = Pt[jx*65 + ty*4 + i];
            float4 v4 = *(float4*)&Vs[jx*64 + tx*4];
            float vv[4] = {v4.x, v4.y, v4.z, v4.w};
#pragma unroll
            for (int i = 0; i < 4; i++)
#pragma unroll
                for (int j = 0; j < 4; j++)
                    o[i][j] = fmaf(pv[i], vv[j], o[i][j]);
        }
    }

    // Epilogue: normalize, write expanded split-bf16 [hi | hi | lo] into g_a2
#pragma unroll
    for (int i = 0; i < 4; i++) {
        float inv = 1.f / l_r[i];
        int r = qt*64 + ty*4 + i;
        size_t base = (size_t)(b*T_ + r) * K3_ + h*64 + tx*4;
#pragma unroll
        for (int j = 0; j < 4; j++) {
            float val = o[i][j] * inv;
            __nv_bfloat16 hi = __float2bfloat16(val);
            __nv_bfloat16 lo = __float2bfloat16(val - __bfloat162float(hi));
            g_a2[base + j]          = hi;
            g_a2[base + C_ + j]     = hi;
            g_a2[base + 2*C_ + j]   = lo;
        }
    }
}

// ---------------------------------------------------------------------------
extern "C" void kernel_launch(void* const* d_in, const int* in_sizes, int n_in,
                              void* d_out, int out_size) {
    const float* x    = (const float*)d_in[0];
    const float* Wqkv = (const float*)d_in[1];
    const float* Wout = (const float*)d_in[2];
    float* out = (float*)d_out;

    // Prep: expand x and weights into split-bf16 form (dsts are device globals,
    // referenced inside the kernels)
    split_expand_kernel<<<(M_*C_/4 + 255)/256, 256>>>(x, M_*C_/4);
    transpose_split_expand_kernel<0><<<dim3(NQKV_/32, C_/32), dim3(32, 8)>>>(Wqkv);
    transpose_split_expand_kernel<1><<<dim3(C_/32, C_/32), dim3(32, 8)>>>(Wout);

    // QKV projection on tensor cores (HMMA)
    mma_gemm_kernel<0><<<dim3(NQKV_/128, M_/128), 256>>>(nullptr);

    // Flash attention (fp32 SIMT)
    {
        const int smem_bytes = (3*64*65 + 64*64) * (int)sizeof(float);
        cudaFuncSetAttribute(attn_kernel, cudaFuncAttributeMaxDynamicSharedMemorySize,
                             smem_bytes);
        attn_kernel<<<dim3(T_/64, B_*H_), 256, smem_bytes>>>();
    }

    // Output projection on tensor cores
    mma_gemm_kernel<1><<<dim3(C_/128, M_/128), 256>>>(out);
}

// round 11
// speedup vs baseline: 2.6891x; 2.6891x over previous
#include <cuda_runtime.h>
#include <cuda_bf16.h>
#include <math.h>
#include <stdint.h>

#define B_ 2
#define T_ 2048
#define C_ 768
#define H_ 12
#define D_ 64
#define M_ (B_*T_)       // 4096
#define NQKV_ (3*C_)     // 2304
#define K3_ (3*C_)       // expanded K = 2304
#define NSLAB_ (K3_/32)  // 72

// ---------------------------------------------------------------------------
// Scratch (allocation-free rule: __device__ globals).
// Referenced ONLY from device code (host shadow-symbol bug, see R8).
// ---------------------------------------------------------------------------
__device__ __align__(256) __nv_bfloat16 g_qh[B_*H_*T_*D_], g_ql[B_*H_*T_*D_]; // [bh][t][d]
__device__ __align__(256) __nv_bfloat16 g_kh[B_*H_*T_*D_], g_kl[B_*H_*T_*D_]; // [bh][t][d]
__device__ __align__(256) __nv_bfloat16 g_vh[B_*H_*T_*D_], g_vl[B_*H_*T_*D_]; // [bh][d][t] (transposed!)
__device__ __align__(256) __nv_bfloat16 g_x2[M_*K3_];      // x expanded [M][3K]: hi|hi|lo
__device__ __align__(256) __nv_bfloat16 g_a2[M_*K3_];      // attn out expanded
__device__ __align__(256) __nv_bfloat16 g_w2q[NQKV_*K3_];  // Wqkv^T expanded [N][3K]: hi|lo|hi
__device__ __align__(256) __nv_bfloat16 g_w2o[C_*K3_];     // Wout^T expanded

__device__ __forceinline__ uint32_t pack_bf(__nv_bfloat16 a, __nv_bfloat16 b) {
    return (uint32_t)__bfloat16_as_ushort(a) | ((uint32_t)__bfloat16_as_ushort(b) << 16);
}

#define MMA_BF16(acc, a, b0, b1) asm volatile( \
    "mma.sync.aligned.m16n8k16.row.col.f32.bf16.bf16.f32 " \
    "{%0,%1,%2,%3}, {%4,%5,%6,%7}, {%8,%9}, {%0,%1,%2,%3};" \
    : "+f"((acc)[0]), "+f"((acc)[1]), "+f"((acc)[2]), "+f"((acc)[3]) \
    : "r"((a)[0]), "r"((a)[1]), "r"((a)[2]), "r"((a)[3]), "r"(b0), "r"(b1))

// ---------------------------------------------------------------------------
// Prep 1: x fp32 [M][C] -> g_x2 bf16 [M][3C] = [hi | hi | lo]
// ---------------------------------------------------------------------------
__global__ void split_expand_kernel(const float* __restrict__ src, int n4) {
    int i = blockIdx.x * blockDim.x + threadIdx.x;
    if (i >= n4) return;
    float4 v = ((const float4*)src)[i];
    float vv[4] = {v.x, v.y, v.z, v.w};
    int idx = i * 4;
    int m = idx / C_, k = idx % C_;
    size_t base = (size_t)m * K3_ + k;
#pragma unroll
    for (int j = 0; j < 4; j++) {
        __nv_bfloat16 hi = __float2bfloat16(vv[j]);
        __nv_bfloat16 lo = __float2bfloat16(vv[j] - __bfloat162float(hi));
        g_x2[base + j]          = hi;
        g_x2[base + C_ + j]     = hi;
        g_x2[base + 2*C_ + j]   = lo;
    }
}

// ---------------------------------------------------------------------------
// Prep 2: W fp32 [K][N] -> Wt bf16 [N][3K] = [hi | lo | hi]
// ---------------------------------------------------------------------------
template<int WHICH>
__global__ void transpose_split_expand_kernel(const float* __restrict__ W) {
    const int K = C_;
    const int N = (WHICH == 0) ? NQKV_ : C_;
    __nv_bfloat16* Bt = (WHICH == 0) ? g_w2q : g_w2o;

    __shared__ float tile[32][33];
    const int c0 = blockIdx.x * 32;
    const int r0 = blockIdx.y * 32;
    const int tx = threadIdx.x, ty = threadIdx.y;
#pragma unroll
    for (int i = 0; i < 4; i++)
        tile[ty + i*8][tx] = W[(size_t)(r0 + ty + i*8) * N + c0 + tx];
    __syncthreads();
#pragma unroll
    for (int i = 0; i < 4; i++) {
        float v = tile[tx][ty + i*8];
        __nv_bfloat16 hi = __float2bfloat16(v);
        __nv_bfloat16 lo = __float2bfloat16(v - __bfloat162float(hi));
        int n = c0 + ty + i*8, k = r0 + tx;
        size_t base = (size_t)n * K3_;
        Bt[base + k]        = hi;
        Bt[base + K + k]    = lo;
        Bt[base + 2*K + k]  = hi;
    }
}

// ---------------------------------------------------------------------------
// HMMA GEMM (proven R9 core): D[M,N] = A'[M,K3] * B'[N,K3]^T
// MODE 0: A=g_x2, B=g_w2q; epilogue writes split-bf16 q/k (packed) and v
//         (transposed d-major).  MODE 1: A=g_a2, B=g_w2o -> outp fp32.
// ---------------------------------------------------------------------------
template<int MODE>
__global__ __launch_bounds__(256) void mma_gemm_kernel(float* __restrict__ outp)
{
    const __nv_bfloat16* __restrict__ A2 = (MODE == 0) ? g_x2 : g_a2;
    const __nv_bfloat16* __restrict__ B2 = (MODE == 0) ? g_w2q : g_w2o;

    __shared__ __align__(16) unsigned char smem[20480];  // A @0, B @10240

    const int tid = threadIdx.x;
    const int wid = tid >> 5, lane = tid & 31;
    const int gid = lane >> 2, tig = lane & 3;
    const int m0 = blockIdx.y << 7, n0 = blockIdx.x << 7;
    const int warp_m = wid & 1, warp_n = wid >> 1;

    const int lr0 = tid >> 2;
    const int lr1 = lr0 + 64;
    const int lc  = (tid & 3) * 8;

    const __nv_bfloat16* Abase  = A2 + (size_t)(m0 + lr0) * K3_ + lc;
    const __nv_bfloat16* Abase1 = A2 + (size_t)(m0 + lr1) * K3_ + lc;
    const __nv_bfloat16* Bbase  = B2 + (size_t)(n0 + lr0) * K3_ + lc;
    const __nv_bfloat16* Bbase1 = B2 + (size_t)(n0 + lr1) * K3_ + lc;

    float acc[4][4][4];
#pragma unroll
    for (int a = 0; a < 4; a++)
#pragma unroll
        for (int b = 0; b < 4; b++)
#pragma unroll
            for (int c = 0; c < 4; c++) acc[a][b][c] = 0.f;

    uint4 pa0 = *(const uint4*)(Abase);
    uint4 pa1 = *(const uint4*)(Abase1);
    uint4 pb0 = *(const uint4*)(Bbase);
    uint4 pb1 = *(const uint4*)(Bbase1);

    for (int ks = 0; ks < NSLAB_; ks++) {
        *(uint4*)&smem[lr0*80 + (tid & 3)*16]          = pa0;
        *(uint4*)&smem[lr1*80 + (tid & 3)*16]          = pa1;
        *(uint4*)&smem[10240 + lr0*80 + (tid & 3)*16]  = pb0;
        *(uint4*)&smem[10240 + lr1*80 + (tid & 3)*16]  = pb1;
        __syncthreads();

        if (ks + 1 < NSLAB_) {
            const int ko = (ks + 1) * 32;
            pa0 = *(const uint4*)(Abase + ko);
            pa1 = *(const uint4*)(Abase1 + ko);
            pb0 = *(const uint4*)(Bbase + ko);
            pb1 = *(const uint4*)(Bbase1 + ko);
        }

#pragma unroll
        for (int kst = 0; kst < 2; kst++) {
            uint32_t af[4][4];
#pragma unroll
            for (int tm = 0; tm < 4; tm++) {
                const int row = warp_m*64 + tm*16 + gid;
                const unsigned char* pa = &smem[row*80 + kst*32 + tig*4];
                af[tm][0] = *(const uint32_t*)(pa);
                af[tm][1] = *(const uint32_t*)(pa + 8*80);
                af[tm][2] = *(const uint32_t*)(pa + 16);
                af[tm][3] = *(const uint32_t*)(pa + 8*80+16);
            }
            uint32_t bfr[2][2][2];
#pragma unroll
            for (int tp = 0; tp < 2; tp++)
#pragma unroll
                for (int hh = 0; hh < 2; hh++) {
                    const int n = warp_n*32 + tp*16 + hh*8 + gid;
                    const unsigned char* pb = &smem[10240 + n*80 + kst*32 + tig*4];
                    bfr[tp][hh][0] = *(const uint32_t*)(pb);
                    bfr[tp][hh][1] = *(const uint32_t*)(pb + 16);
                }
#pragma unroll
            for (int tm = 0; tm < 4; tm++)
#pragma unroll
                for (int tn = 0; tn < 4; tn++)
                    MMA_BF16(acc[tm][tn], af[tm], bfr[tn>>1][tn&1][0], bfr[tn>>1][tn&1][1]);
        }
        __syncthreads();
    }

    // ---- epilogue ----
#pragma unroll
    for (int tm = 0; tm < 4; tm++) {
        const int r0_ = m0 + warp_m*64 + tm*16 + gid;
#pragma unroll
        for (int tn = 0; tn < 4; tn++) {
            const int col = n0 + warp_n*32 + tn*8 + tig*2;
            if (MODE == 1) {
                float2 v0 = {acc[tm][tn][0], acc[tm][tn][1]};
                float2 v1 = {acc[tm][tn][2], acc[tm][tn][3]};
                *(float2*)&outp[(size_t)r0_ * C_ + col]       = v0;
                *(float2*)&outp[(size_t)(r0_ + 8) * C_ + col] = v1;
            } else {
                const int seg = n0 / C_;
                const int nrel = col - seg * C_;
                const int hh = nrel >> 6, dd = nrel & 63;
#pragma unroll
                for (int half = 0; half < 2; half++) {
                    const int m = r0_ + half * 8;
                    const int bb = m >> 11, tt = m & (T_ - 1);
                    const int bhh = bb*H_ + hh;
                    float v0 = acc[tm][tn][half*2], v1 = acc[tm][tn][half*2 + 1];
                    __nv_bfloat16 h0 = __float2bfloat16(v0);
                    __nv_bfloat16 h1 = __float2bfloat16(v1);
                    __nv_bfloat16 l0 = __float2bfloat16(v0 - __bfloat162float(h0));
                    __nv_bfloat16 l1 = __float2bfloat16(v1 - __bfloat162float(h1));
                    if (seg == 0) {
                        size_t base = ((size_t)bhh*T_ + tt)*D_ + dd;
                        *(uint32_t*)&g_qh[base] = pack_bf(h0, h1);
                        *(uint32_t*)&g_ql[base] = pack_bf(l0, l1);
                    } else if (seg == 1) {
                        size_t base = ((size_t)bhh*T_ + tt)*D_ + dd;
                        *(uint32_t*)&g_kh[base] = pack_bf(h0, h1);
                        *(uint32_t*)&g_kl[base] = pack_bf(l0, l1);
                    } else {
                        size_t base = ((size_t)bhh*D_ + dd)*T_ + tt;  // d-major
                        g_vh[base]      = h0;  g_vl[base]      = l0;
                        g_vh[base + T_] = h1;  g_vl[base + T_] = l1;
                    }
                }
            }
        }
    }
}

// ---------------------------------------------------------------------------
// HMMA causal flash attention.  CTA = 128 thr (4 warps), Q tile 64 rows,
// warp tile 16x64.  Split-bf16 3-term for QK^T and PV.  Softmax in fragment
// registers; P -> A-operand repack is register-only (C-frag == A-frag layout).
// smem: Qh,Ql,Kh,Kl (natural [t][d]) + Vh,Vl (d-major [d][t]); pitch 144.
// ---------------------------------------------------------------------------
#define APITCH 144
#define QH_OFF 0
#define QL_OFF 9216
#define KH_OFF 18432
#define KL_OFF 27648
#define VH_OFF 36864
#define VL_OFF 46080
#define ATTN_SMEM 55296

__global__ __launch_bounds__(128) void attn_mma_kernel() {
    extern __shared__ unsigned char smem[];
    const int tid = threadIdx.x;
    const int wid = tid >> 5, lane = tid & 31;
    const int gid = lane >> 2, tig = lane & 3;
    const int bh = blockIdx.y;
    const int b = bh / H_, h = bh % H_;
    const int qt = (int)(gridDim.x - 1) - (int)blockIdx.x;

    const size_t qkbase = (size_t)bh * T_ * D_;
    const size_t vbase  = (size_t)bh * D_ * T_;

    const int lrow = tid >> 1, lhalf = tid & 1;   // cooperative loads: 64B each

    // Load Q tile (64x64 hi/lo), once
    {
        const size_t g = qkbase + (size_t)(qt*64 + lrow)*D_ + lhalf*32;
        const uint4* sh = (const uint4*)(g_qh + g);
        const uint4* sl = (const uint4*)(g_ql + g);
        uint4* dh = (uint4*)(smem + QH_OFF + lrow*APITCH + lhalf*64);
        uint4* dl = (uint4*)(smem + QL_OFF + lrow*APITCH + lhalf*64);
#pragma unroll
        for (int i = 0; i < 4; i++) { dh[i] = sh[i]; dl[i] = sl[i]; }
    }

    float m0 = -1e30f, m1 = -1e30f, l0 = 0.f, l1 = 0.f;
    float o[8][4];
#pragma unroll
    for (int d = 0; d < 8; d++)
#pragma unroll
        for (int c = 0; c < 4; c++) o[d][c] = 0.f;

    const int arow = wid*16 + gid;         // A-fragment base row within tile
    const int grow0 = qt*64 + arow;        // absolute q row (frag rows 0-7 part)

    for (int kt = 0; kt <= qt; kt++) {
        __syncthreads();
        // Load K (natural) and V (d-major) hi/lo slabs
        {
            const size_t gk = qkbase + (size_t)(kt*64 + lrow)*D_ + lhalf*32;
            const uint4* skh = (const uint4*)(g_kh + gk);
            const uint4* skl = (const uint4*)(g_kl + gk);
            uint4* dkh = (uint4*)(smem + KH_OFF + lrow*APITCH + lhalf*64);
            uint4* dkl = (uint4*)(smem + KL_OFF + lrow*APITCH + lhalf*64);
            const size_t gv = vbase + (size_t)lrow*T_ + kt*64 + lhalf*32;
            const uint4* svh = (const uint4*)(g_vh + gv);
            const uint4* svl = (const uint4*)(g_vl + gv);
            uint4* dvh = (uint4*)(smem + VH_OFF + lrow*APITCH + lhalf*64);
            uint4* dvl = (uint4*)(smem + VL_OFF + lrow*APITCH + lhalf*64);
#pragma unroll
            for (int i = 0; i < 4; i++) {
                dkh[i] = skh[i]; dkl[i] = skl[i];
                dvh[i] = svh[i]; dvl[i] = svl[i];
            }
        }
        __syncthreads();

        // ---- S = Q K^T (3-term split) ----
        float s[8][4];
#pragma unroll
        for (int nb = 0; nb < 8; nb++)
#pragma unroll
            for (int c = 0; c < 4; c++) s[nb][c] = 0.f;

#pragma unroll
        for (int kc = 0; kc < 4; kc++) {
            uint32_t ah[4], al[4];
            {
                const unsigned char* pa = smem + QH_OFF + arow*APITCH + kc*32 + tig*4;
                ah[0] = *(const uint32_t*)(pa);
                ah[1] = *(const uint32_t*)(pa + 8*APITCH);
                ah[2] = *(const uint32_t*)(pa + 16);
                ah[3] = *(const uint32_t*)(pa + 8*APITCH + 16);
                const unsigned char* pl = smem + QL_OFF + arow*APITCH + kc*32 + tig*4;
                al[0] = *(const uint32_t*)(pl);
                al[1] = *(const uint32_t*)(pl + 8*APITCH);
                al[2] = *(const uint32_t*)(pl + 16);
                al[3] = *(const uint32_t*)(pl + 8*APITCH + 16);
            }
#pragma unroll
            for (int nb = 0; nb < 8; nb++) {
                const int n = nb*8 + gid;
                const unsigned char* pbh = smem + KH_OFF + n*APITCH + kc*32 + tig*4;
                const unsigned char* pbl = smem + KL_OFF + n*APITCH + kc*32 + tig*4;
                uint32_t bh0 = *(const uint32_t*)(pbh);
                uint32_t bh1 = *(const uint32_t*)(pbh + 16);
                uint32_t bl0 = *(const uint32_t*)(pbl);
                uint32_t bl1 = *(const uint32_t*)(pbl + 16);
                MMA_BF16(s[nb], ah, bh0, bh1);
                MMA_BF16(s[nb], ah, bl0, bl1);
                MMA_BF16(s[nb], al, bh0, bh1);
            }
        }

        // ---- mask + scale ----
        const float scale = 0.125f;
        if (kt == qt) {
#pragma unroll
            for (int nb = 0; nb < 8; nb++) {
                const int colb = kt*64 + nb*8 + tig*2;
                s[nb][0] = (colb     <= grow0    ) ? s[nb][0]*scale : -1e30f;
                s[nb][1] = (colb + 1 <= grow0    ) ? s[nb][1]*scale : -1e30f;
                s[nb][2] = (colb     <= grow0 + 8) ? s[nb][2]*scale : -1e30f;
                s[nb][3] = (colb + 1 <= grow0 + 8) ? s[nb][3]*scale : -1e30f;
            }
        } else {
#pragma unroll
            for (int nb = 0; nb < 8; nb++)
#pragma unroll
                for (int c = 0; c < 4; c++) s[nb][c] *= scale;
        }

        // ---- online softmax (rows gid / gid+8, quad-local reduce) ----
        float mx0 = -1e30f, mx1 = -1e30f;
#pragma unroll
        for (int nb = 0; nb < 8; nb++) {
            mx0 = fmaxf(mx0, fmaxf(s[nb][0], s[nb][1]));
            mx1 = fmaxf(mx1, fmaxf(s[nb][2], s[nb][3]));
        }
#pragma unroll
        for (int off = 1; off <= 2; off <<= 1) {
            mx0 = fmaxf(mx0, __shfl_xor_sync(0xffffffffu, mx0, off));
            mx1 = fmaxf(mx1, __shfl_xor_sync(0xffffffffu, mx1, off));
        }
        const float mn0 = fmaxf(m0, mx0), mn1 = fmaxf(m1, mx1);
        const float cr0 = __expf(m0 - mn0), cr1 = __expf(m1 - mn1);
        float sum0 = 0.f, sum1 = 0.f;
#pragma unroll
        for (int nb = 0; nb < 8; nb++) {
            s[nb][0] = __expf(s[nb][0] - mn0);
            s[nb][1] = __expf(s[nb][1] - mn0);
            s[nb][2] = __expf(s[nb][2] - mn1);
            s[nb][3] = __expf(s[nb][3] - mn1);
            sum0 += s[nb][0] + s[nb][1];
            sum1 += s[nb][2] + s[nb][3];
        }
#pragma unroll
        for (int off = 1; off <= 2; off <<= 1) {
            sum0 += __shfl_xor_sync(0xffffffffu, sum0, off);
            sum1 += __shfl_xor_sync(0xffffffffu, sum1, off);
        }
        l0 = l0 * cr0 + sum0;  m0 = mn0;
        l1 = l1 * cr1 + sum1;  m1 = mn1;
#pragma unroll
        for (int db = 0; db < 8; db++) {
            o[db][0] *= cr0; o[db][1] *= cr0;
            o[db][2] *= cr1; o[db][3] *= cr1;
        }

        // ---- P -> A-fragments (register-only; C-frag layout == A-frag layout)
        uint32_t ph[4][4], pl[4][4];
#pragma unroll
        for (int kc = 0; kc < 4; kc++) {
#pragma unroll
            for (int part = 0; part < 2; part++) {       // part0: k 0-7 (nb=2kc), part1: k 8-15
                const int nb = 2*kc + part;
                __nv_bfloat16 h0 = __float2bfloat16(s[nb][0]);
                __nv_bfloat16 h1 = __float2bfloat16(s[nb][1]);
                __nv_bfloat16 h2 = __float2bfloat16(s[nb][2]);
                __nv_bfloat16 h3 = __float2bfloat16(s[nb][3]);
                ph[kc][0 + part*2] = pack_bf(h0, h1);    // row gid
                ph[kc][1 + part*2] = pack_bf(h2, h3);    // row gid+8
                pl[kc][0 + part*2] = pack_bf(
                    __float2bfloat16(s[nb][0] - __bfloat162float(h0)),
                    __float2bfloat16(s[nb][1] - __bfloat162float(h1)));
                pl[kc][1 + part*2] = pack_bf(
                    __float2bfloat16(s[nb][2] - __bfloat162float(h2)),
                    __float2bfloat16(s[nb][3] - __bfloat162float(h3)));
            }
        }

        // ---- O += P V (3-term split) ----
#pragma unroll
        for (int kc = 0; kc < 4; kc++) {
#pragma unroll
            for (int db = 0; db < 8; db++) {
                const int n = db*8 + gid;                 // n = d
                const unsigned char* pbh = smem + VH_OFF + n*APITCH + kc*32 + tig*4;
                const unsigned char* pbl = smem + VL_OFF + n*APITCH + kc*32 + tig*4;
                uint32_t bh0 = *(const uint32_t*)(pbh);
                uint32_t bh1 = *(const uint32_t*)(pbh + 16);
                uint32_t bl0 = *(const uint32_t*)(pbl);
                uint32_t bl1 = *(const uint32_t*)(pbl + 16);
                MMA_BF16(o[db], ph[kc], bh0, bh1);
                MMA_BF16(o[db], ph[kc], bl0, bl1);
                MMA_BF16(o[db], pl[kc], bh0, bh1);
            }
        }
    }

    // ---- epilogue: normalize, write expanded split-bf16 [hi|hi|lo] -> g_a2
    const float i0 = 1.f / l0, i1 = 1.f / l1;
    const int gr = b*T_ + grow0;
#pragma unroll
    for (int db = 0; db < 8; db++) {
#pragma unroll
        for (int c = 0; c < 4; c++) {
            const float val = o[db][c] * ((c < 2) ? i0 : i1);
            const int row = (c < 2) ? gr : gr + 8;
            const int col = h*64 + db*8 + tig*2 + (c & 1);
            const size_t base = (size_t)row * K3_ + col;
            __nv_bfloat16 hi = __float2bfloat16(val);
            __nv_bfloat16 lo = __float2bfloat16(val - __bfloat162float(hi));
            g_a2[base]        = hi;
            g_a2[base + C_]   = hi;
            g_a2[base + 2*C_] = lo;
        }
    }
}

// ---------------------------------------------------------------------------
extern "C" void kernel_launch(void* const* d_in, const int* in_sizes, int n_in,
                              void* d_out, int out_size) {
    const float* x    = (const float*)d_in[0];
    const float* Wqkv = (const float*)d_in[1];
    const float* Wout = (const float*)d_in[2];
    float* out = (float*)d_out;

    split_expand_kernel<<<(M_*C_/4 + 255)/256, 256>>>(x, M_*C_/4);
    transpose_split_expand_kernel<0><<<dim3(NQKV_/32, C_/32), dim3(32, 8)>>>(Wqkv);
    transpose_split_expand_kernel<1><<<dim3(C_/32, C_/32), dim3(32, 8)>>>(Wout);

    // QKV projection (HMMA), emits split-bf16 q/k/v
    mma_gemm_kernel<0><<<dim3(NQKV_/128, M_/128), 256>>>(nullptr);

    // Flash attention on tensor cores
    cudaFuncSetAttribute(attn_mma_kernel, cudaFuncAttributeMaxDynamicSharedMemorySize,
                         ATTN_SMEM);
    attn_mma_kernel<<<dim3(T_/64, B_*H_), 128, ATTN_SMEM>>>();

    // Output projection (HMMA)
    mma_gemm_kernel<1><<<dim3(C_/128, M_/128), 256>>>(out);
}

// round 12
// speedup vs baseline: 2.8092x; 1.0447x over previous
#include <cuda_runtime.h>
#include <cuda_bf16.h>
#include <math.h>
#include <stdint.h>

#define B_ 2
#define T_ 2048
#define C_ 768
#define H_ 12
#define D_ 64
#define M_ (B_*T_)       // 4096
#define NQKV_ (3*C_)     // 2304
#define K3_ (3*C_)       // expanded K = 2304
#define NSLAB_ (K3_/32)  // 72

// ---------------------------------------------------------------------------
// Scratch (allocation-free rule: __device__ globals).
// Referenced ONLY from device code (host shadow-symbol bug, see R8).
// ---------------------------------------------------------------------------
__device__ __align__(256) __nv_bfloat16 g_qh[B_*H_*T_*D_], g_ql[B_*H_*T_*D_]; // [bh][t][d]
__device__ __align__(256) __nv_bfloat16 g_kh[B_*H_*T_*D_], g_kl[B_*H_*T_*D_]; // [bh][t][d]
__device__ __align__(256) __nv_bfloat16 g_vh[B_*H_*T_*D_], g_vl[B_*H_*T_*D_]; // [bh][d][t] (transposed!)
__device__ __align__(256) __nv_bfloat16 g_x2[M_*K3_];      // x expanded [M][3K]: hi|hi|lo
__device__ __align__(256) __nv_bfloat16 g_a2[M_*K3_];      // attn out expanded
__device__ __align__(256) __nv_bfloat16 g_w2q[NQKV_*K3_];  // Wqkv^T expanded [N][3K]: hi|lo|hi
__device__ __align__(256) __nv_bfloat16 g_w2o[C_*K3_];     // Wout^T expanded

__device__ __forceinline__ uint32_t pack_bf(__nv_bfloat16 a, __nv_bfloat16 b) {
    return (uint32_t)__bfloat16_as_ushort(a) | ((uint32_t)__bfloat16_as_ushort(b) << 16);
}
__device__ __forceinline__ uint32_t smem_u32(const void* p) {
    uint32_t a;
    asm("{ .reg .u64 t; cvta.to.shared.u64 t, %1; cvt.u32.u64 %0, t; }" : "=r"(a) : "l"(p));
    return a;
}
__device__ __forceinline__ void cp16(uint32_t dst, const void* src) {
    asm volatile("cp.async.cg.shared.global [%0], [%1], 16;" :: "r"(dst), "l"(src));
}
#define CP_COMMIT() asm volatile("cp.async.commit_group;")
#define CP_WAIT(n)  asm volatile("cp.async.wait_group %0;" :: "n"(n))

#define MMA_BF16(acc, a, b0, b1) asm volatile( \
    "mma.sync.aligned.m16n8k16.row.col.f32.bf16.bf16.f32 " \
    "{%0,%1,%2,%3}, {%4,%5,%6,%7}, {%8,%9}, {%0,%1,%2,%3};" \
    : "+f"((acc)[0]), "+f"((acc)[1]), "+f"((acc)[2]), "+f"((acc)[3]) \
    : "r"((a)[0]), "r"((a)[1]), "r"((a)[2]), "r"((a)[3]), "r"(b0), "r"(b1))

#define LDMX4(r, addr) asm volatile( \
    "ldmatrix.sync.aligned.m8n8.x4.shared.b16 {%0,%1,%2,%3}, [%4];" \
    : "=r"((r)[0]), "=r"((r)[1]), "=r"((r)[2]), "=r"((r)[3]) : "r"(addr))

// ---------------------------------------------------------------------------
// Prep 1: x fp32 [M][C] -> g_x2 bf16 [M][3C] = [hi | hi | lo]
// ---------------------------------------------------------------------------
__global__ void split_expand_kernel(const float* __restrict__ src, int n4) {
    int i = blockIdx.x * blockDim.x + threadIdx.x;
    if (i >= n4) return;
    float4 v = ((const float4*)src)[i];
    float vv[4] = {v.x, v.y, v.z, v.w};
    int idx = i * 4;
    int m = idx / C_, k = idx % C_;
    size_t base = (size_t)m * K3_ + k;
#pragma unroll
    for (int j = 0; j < 4; j++) {
        __nv_bfloat16 hi = __float2bfloat16(vv[j]);
        __nv_bfloat16 lo = __float2bfloat16(vv[j] - __bfloat162float(hi));
        g_x2[base + j]          = hi;
        g_x2[base + C_ + j]     = hi;
        g_x2[base + 2*C_ + j]   = lo;
    }
}

// ---------------------------------------------------------------------------
// Prep 2: W fp32 [K][N] -> Wt bf16 [N][3K] = [hi | lo | hi]
// ---------------------------------------------------------------------------
template<int WHICH>
__global__ void transpose_split_expand_kernel(const float* __restrict__ W) {
    const int K = C_;
    const int N = (WHICH == 0) ? NQKV_ : C_;
    __nv_bfloat16* Bt = (WHICH == 0) ? g_w2q : g_w2o;

    __shared__ float tile[32][33];
    const int c0 = blockIdx.x * 32;
    const int r0 = blockIdx.y * 32;
    const int tx = threadIdx.x, ty = threadIdx.y;
#pragma unroll
    for (int i = 0; i < 4; i++)
        tile[ty + i*8][tx] = W[(size_t)(r0 + ty + i*8) * N + c0 + tx];
    __syncthreads();
#pragma unroll
    for (int i = 0; i < 4; i++) {
        float v = tile[tx][ty + i*8];
        __nv_bfloat16 hi = __float2bfloat16(v);
        __nv_bfloat16 lo = __float2bfloat16(v - __bfloat162float(hi));
        int n = c0 + ty + i*8, k = r0 + tx;
        size_t base = (size_t)n * K3_;
        Bt[base + k]        = hi;
        Bt[base + K + k]    = lo;
        Bt[base + 2*K + k]  = hi;
    }
}

// ---------------------------------------------------------------------------
// HMMA GEMM, 3-stage cp.async pipeline + ldmatrix fragment loads.
// D[M,N] = A'[M,K3] * B'[N,K3]^T.  128x128 CTA tile, 8 warps, K-slab 32.
// smem: 3 stages x (A 128x80 + B 128x80) = 61440 B dynamic.
// MODE 0: A=g_x2, B=g_w2q; epilogue writes split-bf16 q/k (packed) + v
//         (d-major).  MODE 1: A=g_a2, B=g_w2o -> outp fp32 [M,C_].
// ---------------------------------------------------------------------------
#define STG_BYTES 20480
#define GEMM_SMEM (3*STG_BYTES)

template<int MODE>
__global__ __launch_bounds__(256) void mma_gemm_kernel(float* __restrict__ outp)
{
    const __nv_bfloat16* __restrict__ A2 = (MODE == 0) ? g_x2 : g_a2;
    const __nv_bfloat16* __restrict__ B2 = (MODE == 0) ? g_w2q : g_w2o;

    extern __shared__ unsigned char smem[];
    const uint32_t sbase = smem_u32(smem);

    const int tid = threadIdx.x;
    const int wid = tid >> 5, lane = tid & 31;
    const int gid = lane >> 2, tig = lane & 3;
    const int m0 = blockIdx.y << 7, n0 = blockIdx.x << 7;
    const int warp_m = wid & 1, warp_n = wid >> 1;

    // cooperative loads: 512 x 16B chunks per matrix over 256 threads
    const int lr0 = tid >> 2;          // rows 0..63
    const int lr1 = lr0 + 64;          // rows 64..127
    const uint32_t sA0 = lr0*80 + (tid & 3)*16;
    const uint32_t sA1 = lr1*80 + (tid & 3)*16;

    const __nv_bfloat16* Abase  = A2 + (size_t)(m0 + lr0) * K3_ + (tid & 3)*8;
    const __nv_bfloat16* Abase1 = A2 + (size_t)(m0 + lr1) * K3_ + (tid & 3)*8;
    const __nv_bfloat16* Bbase  = B2 + (size_t)(n0 + lr0) * K3_ + (tid & 3)*8;
    const __nv_bfloat16* Bbase1 = B2 + (size_t)(n0 + lr1) * K3_ + (tid & 3)*8;

    float acc[4][4][4];
#pragma unroll
    for (int a = 0; a < 4; a++)
#pragma unroll
        for (int b = 0; b < 4; b++)
#pragma unroll
            for (int c = 0; c < 4; c++) acc[a][b][c] = 0.f;

    auto issue = [&](int ks) {
        const uint32_t st = sbase + (uint32_t)(ks % 3) * STG_BYTES;
        const size_t ko = (size_t)ks * 32;
        cp16(st + sA0,          Abase  + ko);
        cp16(st + sA1,          Abase1 + ko);
        cp16(st + 10240 + sA0,  Bbase  + ko);
        cp16(st + 10240 + sA1,  Bbase1 + ko);
        CP_COMMIT();
    };

    issue(0);
    issue(1);

    // per-warp ldmatrix base offsets (R6 formulas; layouts verified vs R9/R11)
    const int a_mrow = warp_m*64 + (lane & 7) + ((lane >> 3) & 1)*8;
    const uint32_t a_koff = (uint32_t)(lane >> 4) * 16;
    const int b_nrow = warp_n*32 + (lane & 7) + ((lane >> 4) & 1)*8;
    const uint32_t b_koff = (uint32_t)((lane >> 3) & 1) * 16;

    for (int ks = 0; ks < NSLAB_; ks++) {
        if (ks + 2 < NSLAB_) issue(ks + 2);
        else                 CP_COMMIT();     // keep group count constant
        CP_WAIT(2);
        __syncthreads();

        const uint32_t bufA = sbase + (uint32_t)(ks % 3) * STG_BYTES;
        const uint32_t bufB = bufA + 10240;

#pragma unroll
        for (int kst = 0; kst < 2; kst++) {
            uint32_t af[4][4];
#pragma unroll
            for (int tm = 0; tm < 4; tm++)
                LDMX4(af[tm], bufA + (a_mrow + tm*16)*80 + kst*32 + a_koff);
            uint32_t bfr[2][4];
#pragma unroll
            for (int tp = 0; tp < 2; tp++)
                LDMX4(bfr[tp], bufB + (b_nrow + tp*16)*80 + kst*32 + b_koff);
#pragma unroll
            for (int tm = 0; tm < 4; tm++)
#pragma unroll
                for (int tn = 0; tn < 4; tn++)
                    MMA_BF16(acc[tm][tn], af[tm],
                             bfr[tn>>1][(tn&1)*2], bfr[tn>>1][(tn&1)*2 + 1]);
        }
        __syncthreads();
    }

    // ---- epilogue ----
#pragma unroll
    for (int tm = 0; tm < 4; tm++) {
        const int r0_ = m0 + warp_m*64 + tm*16 + gid;
#pragma unroll
        for (int tn = 0; tn < 4; tn++) {
            const int col = n0 + warp_n*32 + tn*8 + tig*2;
            if (MODE == 1) {
                float2 v0 = {acc[tm][tn][0], acc[tm][tn][1]};
                float2 v1 = {acc[tm][tn][2], acc[tm][tn][3]};
                *(float2*)&outp[(size_t)r0_ * C_ + col]       = v0;
                *(float2*)&outp[(size_t)(r0_ + 8) * C_ + col] = v1;
            } else {
                const int seg = n0 / C_;
                const int nrel = col - seg * C_;
                const int hh = nrel >> 6, dd = nrel & 63;
#pragma unroll
                for (int half = 0; half < 2; half++) {
                    const int m = r0_ + half * 8;
                    const int bb = m >> 11, tt = m & (T_ - 1);
                    const int bhh = bb*H_ + hh;
                    float v0 = acc[tm][tn][half*2], v1 = acc[tm][tn][half*2 + 1];
                    __nv_bfloat16 h0 = __float2bfloat16(v0);
                    __nv_bfloat16 h1 = __float2bfloat16(v1);
                    __nv_bfloat16 l0 = __float2bfloat16(v0 - __bfloat162float(h0));
                    __nv_bfloat16 l1 = __float2bfloat16(v1 - __bfloat162float(h1));
                    if (seg == 0) {
                        size_t base = ((size_t)bhh*T_ + tt)*D_ + dd;
                        *(uint32_t*)&g_qh[base] = pack_bf(h0, h1);
                        *(uint32_t*)&g_ql[base] = pack_bf(l0, l1);
                    } else if (seg == 1) {
                        size_t base = ((size_t)bhh*T_ + tt)*D_ + dd;
                        *(uint32_t*)&g_kh[base] = pack_bf(h0, h1);
                        *(uint32_t*)&g_kl[base] = pack_bf(l0, l1);
                    } else {
                        size_t base = ((size_t)bhh*D_ + dd)*T_ + tt;  // d-major
                        g_vh[base]      = h0;  g_vl[base]      = l0;
                        g_vh[base + T_] = h1;  g_vl[base + T_] = l1;
                    }
                }
            }
        }
    }
}

// ---------------------------------------------------------------------------
// HMMA causal flash attention (R11, passed — unchanged).
// ---------------------------------------------------------------------------
#define APITCH 144
#define QH_OFF 0
#define QL_OFF 9216
#define KH_OFF 18432
#define KL_OFF 27648
#define VH_OFF 36864
#define VL_OFF 46080
#define ATTN_SMEM 55296

__global__ __launch_bounds__(128) void attn_mma_kernel() {
    extern __shared__ unsigned char smem[];
    const int tid = threadIdx.x;
    const int wid = tid >> 5, lane = tid & 31;
    const int gid = lane >> 2, tig = lane & 3;
    const int bh = blockIdx.y;
    const int b = bh / H_, h = bh % H_;
    const int qt = (int)(gridDim.x - 1) - (int)blockIdx.x;

    const size_t qkbase = (size_t)bh * T_ * D_;
    const size_t vbase  = (size_t)bh * D_ * T_;

    const int lrow = tid >> 1, lhalf = tid & 1;

    {
        const size_t g = qkbase + (size_t)(qt*64 + lrow)*D_ + lhalf*32;
        const uint4* sh = (const uint4*)(g_qh + g);
        const uint4* sl = (const uint4*)(g_ql + g);
        uint4* dh = (uint4*)(smem + QH_OFF + lrow*APITCH + lhalf*64);
        uint4* dl = (uint4*)(smem + QL_OFF + lrow*APITCH + lhalf*64);
#pragma unroll
        for (int i = 0; i < 4; i++) { dh[i] = sh[i]; dl[i] = sl[i]; }
    }

    float m0 = -1e30f, m1 = -1e30f, l0 = 0.f, l1 = 0.f;
    float o[8][4];
#pragma unroll
    for (int d = 0; d < 8; d++)
#pragma unroll
        for (int c = 0; c < 4; c++) o[d][c] = 0.f;

    const int arow = wid*16 + gid;
    const int grow0 = qt*64 + arow;

    for (int kt = 0; kt <= qt; kt++) {
        __syncthreads();
        {
            const size_t gk = qkbase + (size_t)(kt*64 + lrow)*D_ + lhalf*32;
            const uint4* skh = (const uint4*)(g_kh + gk);
            const uint4* skl = (const uint4*)(g_kl + gk);
            uint4* dkh = (uint4*)(smem + KH_OFF + lrow*APITCH + lhalf*64);
            uint4* dkl = (uint4*)(smem + KL_OFF + lrow*APITCH + lhalf*64);
            const size_t gv = vbase + (size_t)lrow*T_ + kt*64 + lhalf*32;
            const uint4* svh = (const uint4*)(g_vh + gv);
            const uint4* svl = (const uint4*)(g_vl + gv);
            uint4* dvh = (uint4*)(smem + VH_OFF + lrow*APITCH + lhalf*64);
            uint4* dvl = (uint4*)(smem + VL_OFF + lrow*APITCH + lhalf*64);
#pragma unroll
            for (int i = 0; i < 4; i++) {
                dkh[i] = skh[i]; dkl[i] = skl[i];
                dvh[i] = svh[i]; dvl[i] = svl[i];
            }
        }
        __syncthreads();

        float s[8][4];
#pragma unroll
        for (int nb = 0; nb < 8; nb++)
#pragma unroll
            for (int c = 0; c < 4; c++) s[nb][c] = 0.f;

#pragma unroll
        for (int kc = 0; kc < 4; kc++) {
            uint32_t ah[4], al[4];
            {
                const unsigned char* pa = smem + QH_OFF + arow*APITCH + kc*32 + tig*4;
                ah[0] = *(const uint32_t*)(pa);
                ah[1] = *(const uint32_t*)(pa + 8*APITCH);
                ah[2] = *(const uint32_t*)(pa + 16);
                ah[3] = *(const uint32_t*)(pa + 8*APITCH + 16);
                const unsigned char* pl = smem + QL_OFF + arow*APITCH + kc*32 + tig*4;
                al[0] = *(const uint32_t*)(pl);
                al[1] = *(const uint32_t*)(pl + 8*APITCH);
                al[2] = *(const uint32_t*)(pl + 16);
                al[3] = *(const uint32_t*)(pl + 8*APITCH + 16);
            }
#pragma unroll
            for (int nb = 0; nb < 8; nb++) {
                const int n = nb*8 + gid;
                const unsigned char* pbh = smem + KH_OFF + n*APITCH + kc*32 + tig*4;
                const unsigned char* pbl = smem + KL_OFF + n*APITCH + kc*32 + tig*4;
                uint32_t bh0 = *(const uint32_t*)(pbh);
                uint32_t bh1 = *(const uint32_t*)(pbh + 16);
                uint32_t bl0 = *(const uint32_t*)(pbl);
                uint32_t bl1 = *(const uint32_t*)(pbl + 16);
                MMA_BF16(s[nb], ah, bh0, bh1);
                MMA_BF16(s[nb], ah, bl0, bl1);
                MMA_BF16(s[nb], al, bh0, bh1);
            }
        }

        const float scale = 0.125f;
        if (kt == qt) {
#pragma unroll
            for (int nb = 0; nb < 8; nb++) {
                const int colb = kt*64 + nb*8 + tig*2;
                s[nb][0] = (colb     <= grow0    ) ? s[nb][0]*scale : -1e30f;
                s[nb][1] = (colb + 1 <= grow0    ) ? s[nb][1]*scale : -1e30f;
                s[nb][2] = (colb     <= grow0 + 8) ? s[nb][2]*scale : -1e30f;
                s[nb][3] = (colb + 1 <= grow0 + 8) ? s[nb][3]*scale : -1e30f;
            }
        } else {
#pragma unroll
            for (int nb = 0; nb < 8; nb++)
#pragma unroll
                for (int c = 0; c < 4; c++) s[nb][c] *= scale;
        }

        float mx0 = -1e30f, mx1 = -1e30f;
#pragma unroll
        for (int nb = 0; nb < 8; nb++) {
            mx0 = fmaxf(mx0, fmaxf(s[nb][0], s[nb][1]));
            mx1 = fmaxf(mx1, fmaxf(s[nb][2], s[nb][3]));
        }
#pragma unroll
        for (int off = 1; off <= 2; off <<= 1) {
            mx0 = fmaxf(mx0, __shfl_xor_sync(0xffffffffu, mx0, off));
            mx1 = fmaxf(mx1, __shfl_xor_sync(0xffffffffu, mx1, off));
        }
        const float mn0 = fmaxf(m0, mx0), mn1 = fmaxf(m1, mx1);
        const float cr0 = __expf(m0 - mn0), cr1 = __expf(m1 - mn1);
        float sum0 = 0.f, sum1 = 0.f;
#pragma unroll
        for (int nb = 0; nb < 8; nb++) {
            s[nb][0] = __expf(s[nb][0] - mn0);
            s[nb][1] = __expf(s[nb][1] - mn0);
            s[nb][2] = __expf(s[nb][2] - mn1);
            s[nb][3] = __expf(s[nb][3] - mn1);
            sum0 += s[nb][0] + s[nb][1];
            sum1 += s[nb][2] + s[nb][3];
        }
#pragma unroll
        for (int off = 1; off <= 2; off <<= 1) {
            sum0 += __shfl_xor_sync(0xffffffffu, sum0, off);
            sum1 += __shfl_xor_sync(0xffffffffu, sum1, off);
        }
        l0 = l0 * cr0 + sum0;  m0 = mn0;
        l1 = l1 * cr1 + sum1;  m1 = mn1;
#pragma unroll
        for (int db = 0; db < 8; db++) {
            o[db][0] *= cr0; o[db][1] *= cr0;
            o[db][2] *= cr1; o[db][3] *= cr1;
        }

        uint32_t ph[4][4], pl[4][4];
#pragma unroll
        for (int kc = 0; kc < 4; kc++) {
#pragma unroll
            for (int part = 0; part < 2; part++) {
                const int nb = 2*kc + part;
                __nv_bfloat16 h0 = __float2bfloat16(s[nb][0]);
                __nv_bfloat16 h1 = __float2bfloat16(s[nb][1]);
                __nv_bfloat16 h2 = __float2bfloat16(s[nb][2]);
                __nv_bfloat16 h3 = __float2bfloat16(s[nb][3]);
                ph[kc][0 + part*2] = pack_bf(h0, h1);
                ph[kc][1 + part*2] = pack_bf(h2, h3);
                pl[kc][0 + part*2] = pack_bf(
                    __float2bfloat16(s[nb][0] - __bfloat162float(h0)),
                    __float2bfloat16(s[nb][1] - __bfloat162float(h1)));
                pl[kc][1 + part*2] = pack_bf(
                    __float2bfloat16(s[nb][2] - __bfloat162float(h2)),
                    __float2bfloat16(s[nb][3] - __bfloat162float(h3)));
            }
        }

#pragma unroll
        for (int kc = 0; kc < 4; kc++) {
#pragma unroll
            for (int db = 0; db < 8; db++) {
                const int n = db*8 + gid;
                const unsigned char* pbh = smem + VH_OFF + n*APITCH + kc*32 + tig*4;
                const unsigned char* pbl = smem + VL_OFF + n*APITCH + kc*32 + tig*4;
                uint32_t bh0 = *(const uint32_t*)(pbh);
                uint32_t bh1 = *(const uint32_t*)(pbh + 16);
                uint32_t bl0 = *(const uint32_t*)(pbl);
                uint32_t bl1 = *(const uint32_t*)(pbl + 16);
                MMA_BF16(o[db], ph[kc], bh0, bh1);
                MMA_BF16(o[db], ph[kc], bl0, bl1);
                MMA_BF16(o[db], pl[kc], bh0, bh1);
            }
        }
    }

    const float i0 = 1.f / l0, i1 = 1.f / l1;
    const int gr = b*T_ + grow0;
#pragma unroll
    for (int db = 0; db < 8; db++) {
#pragma unroll
        for (int c = 0; c < 4; c++) {
            const float val = o[db][c] * ((c < 2) ? i0 : i1);
            const int row = (c < 2) ? gr : gr + 8;
            const int col = h*64 + db*8 + tig*2 + (c & 1);
            const size_t base = (size_t)row * K3_ + col;
            __nv_bfloat16 hi = __float2bfloat16(val);
            __nv_bfloat16 lo = __float2bfloat16(val - __bfloat162float(hi));
            g_a2[base]        = hi;
            g_a2[base + C_]   = hi;
            g_a2[base + 2*C_] = lo;
        }
    }
}

// ---------------------------------------------------------------------------
extern "C" void kernel_launch(void* const* d_in, const int* in_sizes, int n_in,
                              void* d_out, int out_size) {
    const float* x    = (const float*)d_in[0];
    const float* Wqkv = (const float*)d_in[1];
    const float* Wout = (const float*)d_in[2];
    float* out = (float*)d_out;

    split_expand_kernel<<<(M_*C_/4 + 255)/256, 256>>>(x, M_*C_/4);
    transpose_split_expand_kernel<0><<<dim3(NQKV_/32, C_/32), dim3(32, 8)>>>(Wqkv);
    transpose_split_expand_kernel<1><<<dim3(C_/32, C_/32), dim3(32, 8)>>>(Wout);

    // QKV projection (HMMA, 3-stage cp.async + ldmatrix)
    cudaFuncSetAttribute(mma_gemm_kernel<0>, cudaFuncAttributeMaxDynamicSharedMemorySize,
                         GEMM_SMEM);
    mma_gemm_kernel<0><<<dim3(NQKV_/128, M_/128), 256, GEMM_SMEM>>>(nullptr);

    // Flash attention on tensor cores
    cudaFuncSetAttribute(attn_mma_kernel, cudaFuncAttributeMaxDynamicSharedMemorySize,
                         ATTN_SMEM);
    attn_mma_kernel<<<dim3(T_/64, B_*H_), 128, ATTN_SMEM>>>();

    // Output projection (HMMA)
    cudaFuncSetAttribute(mma_gemm_kernel<1>, cudaFuncAttributeMaxDynamicSharedMemorySize,
                         GEMM_SMEM);
    mma_gemm_kernel<1><<<dim3(C_/128, M_/128), 256, GEMM_SMEM>>>(out);
}

// round 13
// speedup vs baseline: 3.0059x; 1.0700x over previous
#include <cuda_runtime.h>
#include <cuda_bf16.h>
#include <math.h>
#include <stdint.h>

#define B_ 2
#define T_ 2048
#define C_ 768
#define H_ 12
#define D_ 64
#define M_ (B_*T_)       // 4096
#define NQKV_ (3*C_)     // 2304
#define K3_ (3*C_)       // expanded K = 2304
#define NSLAB_ (K3_/32)  // 72

// ---------------------------------------------------------------------------
// Scratch (allocation-free rule: __device__ globals).
// Referenced ONLY from device code (host shadow-symbol bug, see R8).
// ---------------------------------------------------------------------------
__device__ __align__(256) __nv_bfloat16 g_qh[B_*H_*T_*D_], g_ql[B_*H_*T_*D_]; // [bh][t][d]
__device__ __align__(256) __nv_bfloat16 g_kh[B_*H_*T_*D_], g_kl[B_*H_*T_*D_]; // [bh][t][d]
__device__ __align__(256) __nv_bfloat16 g_vh[B_*H_*T_*D_], g_vl[B_*H_*T_*D_]; // [bh][d][t] (transposed!)
__device__ __align__(256) __nv_bfloat16 g_x2[M_*K3_];      // x expanded [M][3K]: hi|hi|lo
__device__ __align__(256) __nv_bfloat16 g_a2[M_*K3_];      // attn out expanded
__device__ __align__(256) __nv_bfloat16 g_w2q[NQKV_*K3_];  // Wqkv^T expanded [N][3K]: hi|lo|hi
__device__ __align__(256) __nv_bfloat16 g_w2o[C_*K3_];     // Wout^T expanded

__device__ __forceinline__ uint32_t pack_bf(__nv_bfloat16 a, __nv_bfloat16 b) {
    return (uint32_t)__bfloat16_as_ushort(a) | ((uint32_t)__bfloat16_as_ushort(b) << 16);
}
__device__ __forceinline__ uint32_t smem_u32(const void* p) {
    uint32_t a;
    asm("{ .reg .u64 t; cvta.to.shared.u64 t, %1; cvt.u32.u64 %0, t; }" : "=r"(a) : "l"(p));
    return a;
}
__device__ __forceinline__ void cp16(uint32_t dst, const void* src) {
    asm volatile("cp.async.cg.shared.global [%0], [%1], 16;" :: "r"(dst), "l"(src));
}
#define CP_COMMIT() asm volatile("cp.async.commit_group;")
#define CP_WAIT(n)  asm volatile("cp.async.wait_group %0;" :: "n"(n))

#define MMA_BF16(acc, a, b0, b1) asm volatile( \
    "mma.sync.aligned.m16n8k16.row.col.f32.bf16.bf16.f32 " \
    "{%0,%1,%2,%3}, {%4,%5,%6,%7}, {%8,%9}, {%0,%1,%2,%3};" \
    : "+f"((acc)[0]), "+f"((acc)[1]), "+f"((acc)[2]), "+f"((acc)[3]) \
    : "r"((a)[0]), "r"((a)[1]), "r"((a)[2]), "r"((a)[3]), "r"(b0), "r"(b1))

#define LDMX4(r, addr) asm volatile( \
    "ldmatrix.sync.aligned.m8n8.x4.shared.b16 {%0,%1,%2,%3}, [%4];" \
    : "=r"((r)[0]), "=r"((r)[1]), "=r"((r)[2]), "=r"((r)[3]) : "r"(addr))

// ---------------------------------------------------------------------------
// Prep 1: x fp32 [M][C] -> g_x2 bf16 [M][3C] = [hi | hi | lo]
// ---------------------------------------------------------------------------
__global__ void split_expand_kernel(const float* __restrict__ src, int n4) {
    int i = blockIdx.x * blockDim.x + threadIdx.x;
    if (i >= n4) return;
    float4 v = ((const float4*)src)[i];
    float vv[4] = {v.x, v.y, v.z, v.w};
    int idx = i * 4;
    int m = idx / C_, k = idx % C_;
    size_t base = (size_t)m * K3_ + k;
#pragma unroll
    for (int j = 0; j < 4; j++) {
        __nv_bfloat16 hi = __float2bfloat16(vv[j]);
        __nv_bfloat16 lo = __float2bfloat16(vv[j] - __bfloat162float(hi));
        g_x2[base + j]          = hi;
        g_x2[base + C_ + j]     = hi;
        g_x2[base + 2*C_ + j]   = lo;
    }
}

// ---------------------------------------------------------------------------
// Prep 2: W fp32 [K][N] -> Wt bf16 [N][3K] = [hi | lo | hi]
// ---------------------------------------------------------------------------
template<int WHICH>
__global__ void transpose_split_expand_kernel(const float* __restrict__ W) {
    const int K = C_;
    const int N = (WHICH == 0) ? NQKV_ : C_;
    __nv_bfloat16* Bt = (WHICH == 0) ? g_w2q : g_w2o;

    __shared__ float tile[32][33];
    const int c0 = blockIdx.x * 32;
    const int r0 = blockIdx.y * 32;
    const int tx = threadIdx.x, ty = threadIdx.y;
#pragma unroll
    for (int i = 0; i < 4; i++)
        tile[ty + i*8][tx] = W[(size_t)(r0 + ty + i*8) * N + c0 + tx];
    __syncthreads();
#pragma unroll
    for (int i = 0; i < 4; i++) {
        float v = tile[tx][ty + i*8];
        __nv_bfloat16 hi = __float2bfloat16(v);
        __nv_bfloat16 lo = __float2bfloat16(v - __bfloat162float(hi));
        int n = c0 + ty + i*8, k = r0 + tx;
        size_t base = (size_t)n * K3_;
        Bt[base + k]        = hi;
        Bt[base + K + k]    = lo;
        Bt[base + 2*K + k]  = hi;
    }
}

// ---------------------------------------------------------------------------
// HMMA GEMM, 3-stage cp.async pipeline + ldmatrix, ONE barrier per slab.
// Loop shape: WAIT(1); sync; compute(stage ks%3); issue(ks+2).
// issue targets stage (ks-1)%3 whose readers all passed this iter's sync.
// ---------------------------------------------------------------------------
#define STG_BYTES 20480
#define GEMM_SMEM (3*STG_BYTES)

template<int MODE>
__global__ __launch_bounds__(256) void mma_gemm_kernel(float* __restrict__ outp)
{
    const __nv_bfloat16* __restrict__ A2 = (MODE == 0) ? g_x2 : g_a2;
    const __nv_bfloat16* __restrict__ B2 = (MODE == 0) ? g_w2q : g_w2o;

    extern __shared__ unsigned char smem[];
    const uint32_t sbase = smem_u32(smem);

    const int tid = threadIdx.x;
    const int wid = tid >> 5, lane = tid & 31;
    const int gid = lane >> 2, tig = lane & 3;
    const int m0 = blockIdx.y << 7, n0 = blockIdx.x << 7;
    const int warp_m = wid & 1, warp_n = wid >> 1;

    const int lr0 = tid >> 2;
    const int lr1 = lr0 + 64;
    const uint32_t sA0 = lr0*80 + (tid & 3)*16;
    const uint32_t sA1 = lr1*80 + (tid & 3)*16;

    const __nv_bfloat16* Abase  = A2 + (size_t)(m0 + lr0) * K3_ + (tid & 3)*8;
    const __nv_bfloat16* Abase1 = A2 + (size_t)(m0 + lr1) * K3_ + (tid & 3)*8;
    const __nv_bfloat16* Bbase  = B2 + (size_t)(n0 + lr0) * K3_ + (tid & 3)*8;
    const __nv_bfloat16* Bbase1 = B2 + (size_t)(n0 + lr1) * K3_ + (tid & 3)*8;

    float acc[4][4][4];
#pragma unroll
    for (int a = 0; a < 4; a++)
#pragma unroll
        for (int b = 0; b < 4; b++)
#pragma unroll
            for (int c = 0; c < 4; c++) acc[a][b][c] = 0.f;

    auto issue = [&](int ks) {
        const uint32_t st = sbase + (uint32_t)(ks % 3) * STG_BYTES;
        const size_t ko = (size_t)ks * 32;
        cp16(st + sA0,          Abase  + ko);
        cp16(st + sA1,          Abase1 + ko);
        cp16(st + 10240 + sA0,  Bbase  + ko);
        cp16(st + 10240 + sA1,  Bbase1 + ko);
        CP_COMMIT();
    };

    issue(0);
    issue(1);

    const int a_mrow = warp_m*64 + (lane & 7) + ((lane >> 3) & 1)*8;
    const uint32_t a_koff = (uint32_t)(lane >> 4) * 16;
    const int b_nrow = warp_n*32 + (lane & 7) + ((lane >> 4) & 1)*8;
    const uint32_t b_koff = (uint32_t)((lane >> 3) & 1) * 16;

    for (int ks = 0; ks < NSLAB_; ks++) {
        CP_WAIT(1);          // group ks complete (ks+1 may be in flight)
        __syncthreads();     // all warps done with stage (ks-1) reads + see stage ks

        const uint32_t bufA = sbase + (uint32_t)(ks % 3) * STG_BYTES;
        const uint32_t bufB = bufA + 10240;

#pragma unroll
        for (int kst = 0; kst < 2; kst++) {
            uint32_t af[4][4];
#pragma unroll
            for (int tm = 0; tm < 4; tm++)
                LDMX4(af[tm], bufA + (a_mrow + tm*16)*80 + kst*32 + a_koff);
            uint32_t bfr[2][4];
#pragma unroll
            for (int tp = 0; tp < 2; tp++)
                LDMX4(bfr[tp], bufB + (b_nrow + tp*16)*80 + kst*32 + b_koff);
#pragma unroll
            for (int tm = 0; tm < 4; tm++)
#pragma unroll
                for (int tn = 0; tn < 4; tn++)
                    MMA_BF16(acc[tm][tn], af[tm],
                             bfr[tn>>1][(tn&1)*2], bfr[tn>>1][(tn&1)*2 + 1]);
        }

        if (ks + 2 < NSLAB_) issue(ks + 2);
        else                 CP_COMMIT();     // keep group count constant
    }

    // ---- epilogue ----
#pragma unroll
    for (int tm = 0; tm < 4; tm++) {
        const int r0_ = m0 + warp_m*64 + tm*16 + gid;
#pragma unroll
        for (int tn = 0; tn < 4; tn++) {
            const int col = n0 + warp_n*32 + tn*8 + tig*2;
            if (MODE == 1) {
                float2 v0 = {acc[tm][tn][0], acc[tm][tn][1]};
                float2 v1 = {acc[tm][tn][2], acc[tm][tn][3]};
                *(float2*)&outp[(size_t)r0_ * C_ + col]       = v0;
                *(float2*)&outp[(size_t)(r0_ + 8) * C_ + col] = v1;
            } else {
                const int seg = n0 / C_;
                const int nrel = col - seg * C_;
                const int hh = nrel >> 6, dd = nrel & 63;
#pragma unroll
                for (int half = 0; half < 2; half++) {
                    const int m = r0_ + half * 8;
                    const int bb = m >> 11, tt = m & (T_ - 1);
                    const int bhh = bb*H_ + hh;
                    float v0 = acc[tm][tn][half*2], v1 = acc[tm][tn][half*2 + 1];
                    __nv_bfloat16 h0 = __float2bfloat16(v0);
                    __nv_bfloat16 h1 = __float2bfloat16(v1);
                    __nv_bfloat16 l0 = __float2bfloat16(v0 - __bfloat162float(h0));
                    __nv_bfloat16 l1 = __float2bfloat16(v1 - __bfloat162float(h1));
                    if (seg == 0) {
                        size_t base = ((size_t)bhh*T_ + tt)*D_ + dd;
                        *(uint32_t*)&g_qh[base] = pack_bf(h0, h1);
                        *(uint32_t*)&g_ql[base] = pack_bf(l0, l1);
                    } else if (seg == 1) {
                        size_t base = ((size_t)bhh*T_ + tt)*D_ + dd;
                        *(uint32_t*)&g_kh[base] = pack_bf(h0, h1);
                        *(uint32_t*)&g_kl[base] = pack_bf(l0, l1);
                    } else {
                        size_t base = ((size_t)bhh*D_ + dd)*T_ + tt;  // d-major
                        g_vh[base]      = h0;  g_vl[base]      = l0;
                        g_vh[base + T_] = h1;  g_vl[base + T_] = l1;
                    }
                }
            }
        }
    }
}

// ---------------------------------------------------------------------------
// HMMA causal flash attention with 2-stage cp.async K/V double buffering.
// Compute body identical to R11/R12 (passed).  smem:
//   Q hi/lo @ 0/9216 (64x144); KV stage s @ 18432 + s*36864:
//   KH +0, KL +9216, VH +18432, VL +27648.   Total 92160 B.
// ---------------------------------------------------------------------------
#define APITCH 144
#define QH_OFF 0
#define QL_OFF 9216
#define KV_OFF 18432
#define KV_STG 36864
#define ATTN_SMEM (KV_OFF + 2*KV_STG)   // 92160

__global__ __launch_bounds__(128) void attn_mma_kernel() {
    extern __shared__ unsigned char smem[];
    const uint32_t sbase = smem_u32(smem);
    const int tid = threadIdx.x;
    const int wid = tid >> 5, lane = tid & 31;
    const int gid = lane >> 2, tig = lane & 3;
    const int bh = blockIdx.y;
    const int b = bh / H_, h = bh % H_;
    const int qt = (int)(gridDim.x - 1) - (int)blockIdx.x;

    const size_t qkbase = (size_t)bh * T_ * D_;
    const size_t vbase  = (size_t)bh * D_ * T_;

    const int lrow = tid >> 1, lhalf = tid & 1;
    const uint32_t sofs = (uint32_t)(lrow*APITCH + lhalf*64);

    auto issue_kv = [&](int kt2) {
        const uint32_t st = sbase + KV_OFF + (uint32_t)(kt2 & 1) * KV_STG;
        const size_t gk = qkbase + (size_t)(kt2*64 + lrow)*D_ + lhalf*32;
        const size_t gv = vbase + (size_t)lrow*T_ + kt2*64 + lhalf*32;
#pragma unroll
        for (int i = 0; i < 4; i++) {
            cp16(st + sofs          + i*16, g_kh + gk + i*8);
            cp16(st + 9216  + sofs  + i*16, g_kl + gk + i*8);
            cp16(st + 18432 + sofs  + i*16, g_vh + gv + i*8);
            cp16(st + 27648 + sofs  + i*16, g_vl + gv + i*8);
        }
        CP_COMMIT();
    };

    // Load Q tile (sync, once)
    {
        const size_t g = qkbase + (size_t)(qt*64 + lrow)*D_ + lhalf*32;
        const uint4* sh = (const uint4*)(g_qh + g);
        const uint4* sl = (const uint4*)(g_ql + g);
        uint4* dh = (uint4*)(smem + QH_OFF + sofs);
        uint4* dl = (uint4*)(smem + QL_OFF + sofs);
#pragma unroll
        for (int i = 0; i < 4; i++) { dh[i] = sh[i]; dl[i] = sl[i]; }
    }

    issue_kv(0);

    float m0 = -1e30f, m1 = -1e30f, l0 = 0.f, l1 = 0.f;
    float o[8][4];
#pragma unroll
    for (int d = 0; d < 8; d++)
#pragma unroll
        for (int c = 0; c < 4; c++) o[d][c] = 0.f;

    const int arow = wid*16 + gid;
    const int grow0 = qt*64 + arow;

    for (int kt = 0; kt <= qt; kt++) {
        __syncthreads();                       // readers of stage kt-1 done
        if (kt + 1 <= qt) issue_kv(kt + 1);
        else              CP_COMMIT();         // constant group count
        CP_WAIT(1);                            // stage kt arrived
        __syncthreads();                       // visible to all warps

        const unsigned char* kv = smem + KV_OFF + (size_t)(kt & 1) * KV_STG;
        const unsigned char* KH = kv;
        const unsigned char* KL = kv + 9216;
        const unsigned char* VH = kv + 18432;
        const unsigned char* VL = kv + 27648;

        float s[8][4];
#pragma unroll
        for (int nb = 0; nb < 8; nb++)
#pragma unroll
            for (int c = 0; c < 4; c++) s[nb][c] = 0.f;

#pragma unroll
        for (int kc = 0; kc < 4; kc++) {
            uint32_t ah[4], al[4];
            {
                const unsigned char* pa = smem + QH_OFF + arow*APITCH + kc*32 + tig*4;
                ah[0] = *(const uint32_t*)(pa);
                ah[1] = *(const uint32_t*)(pa + 8*APITCH);
                ah[2] = *(const uint32_t*)(pa + 16);
                ah[3] = *(const uint32_t*)(pa + 8*APITCH + 16);
                const unsigned char* pl = smem + QL_OFF + arow*APITCH + kc*32 + tig*4;
                al[0] = *(const uint32_t*)(pl);
                al[1] = *(const uint32_t*)(pl + 8*APITCH);
                al[2] = *(const uint32_t*)(pl + 16);
                al[3] = *(const uint32_t*)(pl + 8*APITCH + 16);
            }
#pragma unroll
            for (int nb = 0; nb < 8; nb++) {
                const int n = nb*8 + gid;
                const unsigned char* pbh = KH + n*APITCH + kc*32 + tig*4;
                const unsigned char* pbl = KL + n*APITCH + kc*32 + tig*4;
                uint32_t bh0 = *(const uint32_t*)(pbh);
                uint32_t bh1 = *(const uint32_t*)(pbh + 16);
                uint32_t bl0 = *(const uint32_t*)(pbl);
                uint32_t bl1 = *(const uint32_t*)(pbl + 16);
                MMA_BF16(s[nb], ah, bh0, bh1);
                MMA_BF16(s[nb], ah, bl0, bl1);
                MMA_BF16(s[nb], al, bh0, bh1);
            }
        }

        const float scale = 0.125f;
        if (kt == qt) {
#pragma unroll
            for (int nb = 0; nb < 8; nb++) {
                const int colb = kt*64 + nb*8 + tig*2;
                s[nb][0] = (colb     <= grow0    ) ? s[nb][0]*scale : -1e30f;
                s[nb][1] = (colb + 1 <= grow0    ) ? s[nb][1]*scale : -1e30f;
                s[nb][2] = (colb     <= grow0 + 8) ? s[nb][2]*scale : -1e30f;
                s[nb][3] = (colb + 1 <= grow0 + 8) ? s[nb][3]*scale : -1e30f;
            }
        } else {
#pragma unroll
            for (int nb = 0; nb < 8; nb++)
#pragma unroll
                for (int c = 0; c < 4; c++) s[nb][c] *= scale;
        }

        float mx0 = -1e30f, mx1 = -1e30f;
#pragma unroll
        for (int nb = 0; nb < 8; nb++) {
            mx0 = fmaxf(mx0, fmaxf(s[nb][0], s[nb][1]));
            mx1 = fmaxf(mx1, fmaxf(s[nb][2], s[nb][3]));
        }
#pragma unroll
        for (int off = 1; off <= 2; off <<= 1) {
            mx0 = fmaxf(mx0, __shfl_xor_sync(0xffffffffu, mx0, off));
            mx1 = fmaxf(mx1, __shfl_xor_sync(0xffffffffu, mx1, off));
        }
        const float mn0 = fmaxf(m0, mx0), mn1 = fmaxf(m1, mx1);
        const float cr0 = __expf(m0 - mn0), cr1 = __expf(m1 - mn1);
        float sum0 = 0.f, sum1 = 0.f;
#pragma unroll
        for (int nb = 0; nb < 8; nb++) {
            s[nb][0] = __expf(s[nb][0] - mn0);
            s[nb][1] = __expf(s[nb][1] - mn0);
            s[nb][2] = __expf(s[nb][2] - mn1);
            s[nb][3] = __expf(s[nb][3] - mn1);
            sum0 += s[nb][0] + s[nb][1];
            sum1 += s[nb][2] + s[nb][3];
        }
#pragma unroll
        for (int off = 1; off <= 2; off <<= 1) {
            sum0 += __shfl_xor_sync(0xffffffffu, sum0, off);
            sum1 += __shfl_xor_sync(0xffffffffu, sum1, off);
        }
        l0 = l0 * cr0 + sum0;  m0 = mn0;
        l1 = l1 * cr1 + sum1;  m1 = mn1;
#pragma unroll
        for (int db = 0; db < 8; db++) {
            o[db][0] *= cr0; o[db][1] *= cr0;
            o[db][2] *= cr1; o[db][3] *= cr1;
        }

        uint32_t ph[4][4], pl[4][4];
#pragma unroll
        for (int kc = 0; kc < 4; kc++) {
#pragma unroll
            for (int part = 0; part < 2; part++) {
                const int nb = 2*kc + part;
                __nv_bfloat16 h0 = __float2bfloat16(s[nb][0]);
                __nv_bfloat16 h1 = __float2bfloat16(s[nb][1]);
                __nv_bfloat16 h2 = __float2bfloat16(s[nb][2]);
                __nv_bfloat16 h3 = __float2bfloat16(s[nb][3]);
                ph[kc][0 + part*2] = pack_bf(h0, h1);
                ph[kc][1 + part*2] = pack_bf(h2, h3);
                pl[kc][0 + part*2] = pack_bf(
                    __float2bfloat16(s[nb][0] - __bfloat162float(h0)),
                    __float2bfloat16(s[nb][1] - __bfloat162float(h1)));
                pl[kc][1 + part*2] = pack_bf(
                    __float2bfloat16(s[nb][2] - __bfloat162float(h2)),
                    __float2bfloat16(s[nb][3] - __bfloat162float(h3)));
            }
        }

#pragma unroll
        for (int kc = 0; kc < 4; kc++) {
#pragma unroll
            for (int db = 0; db < 8; db++) {
                const int n = db*8 + gid;
                const unsigned char* pbh = VH + n*APITCH + kc*32 + tig*4;
                const unsigned char* pbl = VL + n*APITCH + kc*32 + tig*4;
                uint32_t bh0 = *(const uint32_t*)(pbh);
                uint32_t bh1 = *(const uint32_t*)(pbh + 16);
                uint32_t bl0 = *(const uint32_t*)(pbl);
                uint32_t bl1 = *(const uint32_t*)(pbl + 16);
                MMA_BF16(o[db], ph[kc], bh0, bh1);
                MMA_BF16(o[db], ph[kc], bl0, bl1);
                MMA_BF16(o[db], pl[kc], bh0, bh1);
            }
        }
    }

    const float i0 = 1.f / l0, i1 = 1.f / l1;
    const int gr = b*T_ + grow0;
#pragma unroll
    for (int db = 0; db < 8; db++) {
#pragma unroll
        for (int c = 0; c < 4; c++) {
            const float val = o[db][c] * ((c < 2) ? i0 : i1);
            const int row = (c < 2) ? gr : gr + 8;
            const int col = h*64 + db*8 + tig*2 + (c & 1);
            const size_t base = (size_t)row * K3_ + col;
            __nv_bfloat16 hi = __float2bfloat16(val);
            __nv_bfloat16 lo = __float2bfloat16(val - __bfloat162float(hi));
            g_a2[base]        = hi;
            g_a2[base + C_]   = hi;
            g_a2[base + 2*C_] = lo;
        }
    }
}

// ---------------------------------------------------------------------------
extern "C" void kernel_launch(void* const* d_in, const int* in_sizes, int n_in,
                              void* d_out, int out_size) {
    const float* x    = (const float*)d_in[0];
    const float* Wqkv = (const float*)d_in[1];
    const float* Wout = (const float*)d_in[2];
    float* out = (float*)d_out;

    split_expand_kernel<<<(M_*C_/4 + 255)/256, 256>>>(x, M_*C_/4);
    transpose_split_expand_kernel<0><<<dim3(NQKV_/32, C_/32), dim3(32, 8)>>>(Wqkv);
    transpose_split_expand_kernel<1><<<dim3(C_/32, C_/32), dim3(32, 8)>>>(Wout);

    // QKV projection (HMMA, 3-stage cp.async + ldmatrix, 1 barrier/slab)
    cudaFuncSetAttribute(mma_gemm_kernel<0>, cudaFuncAttributeMaxDynamicSharedMemorySize,
                         GEMM_SMEM);
    mma_gemm_kernel<0><<<dim3(NQKV_/128, M_/128), 256, GEMM_SMEM>>>(nullptr);

    // Flash attention on tensor cores (2-stage async K/V)
    cudaFuncSetAttribute(attn_mma_kernel, cudaFuncAttributeMaxDynamicSharedMemorySize,
                         ATTN_SMEM);
    attn_mma_kernel<<<dim3(T_/64, B_*H_), 128, ATTN_SMEM>>>();

    // Output projection (HMMA)
    cudaFuncSetAttribute(mma_gemm_kernel<1>, cudaFuncAttributeMaxDynamicSharedMemorySize,
                         GEMM_SMEM);
    mma_gemm_kernel<1><<<dim3(C_/128, M_/128), 256, GEMM_SMEM>>>(out);
}

// round 14
// speedup vs baseline: 3.1776x; 1.0571x over previous
#include <cuda_runtime.h>
#include <cuda_bf16.h>
#include <math.h>
#include <stdint.h>

#define B_ 2
#define T_ 2048
#define C_ 768
#define H_ 12
#define D_ 64
#define M_ (B_*T_)       // 4096
#define NQKV_ (3*C_)     // 2304
#define K3_ (3*C_)       // expanded K = 2304
#define KS2 64           // k-elems per GEMM slab
#define NSLAB2 (K3_/KS2) // 36

// ---------------------------------------------------------------------------
// Scratch (allocation-free rule: __device__ globals).
// Referenced ONLY from device code (host shadow-symbol bug, see R8).
// ---------------------------------------------------------------------------
__device__ __align__(256) __nv_bfloat16 g_qh[B_*H_*T_*D_], g_ql[B_*H_*T_*D_]; // [bh][t][d]
__device__ __align__(256) __nv_bfloat16 g_kh[B_*H_*T_*D_], g_kl[B_*H_*T_*D_]; // [bh][t][d]
__device__ __align__(256) __nv_bfloat16 g_vh[B_*H_*T_*D_], g_vl[B_*H_*T_*D_]; // [bh][d][t] (transposed!)
__device__ __align__(256) __nv_bfloat16 g_x2[M_*K3_];      // x expanded [M][3K]: hi|hi|lo
__device__ __align__(256) __nv_bfloat16 g_a2[M_*K3_];      // attn out expanded
__device__ __align__(256) __nv_bfloat16 g_w2q[NQKV_*K3_];  // Wqkv^T expanded [N][3K]: hi|lo|hi
__device__ __align__(256) __nv_bfloat16 g_w2o[C_*K3_];     // Wout^T expanded

__device__ __forceinline__ uint32_t pack_bf(__nv_bfloat16 a, __nv_bfloat16 b) {
    return (uint32_t)__bfloat16_as_ushort(a) | ((uint32_t)__bfloat16_as_ushort(b) << 16);
}
__device__ __forceinline__ uint32_t smem_u32(const void* p) {
    uint32_t a;
    asm("{ .reg .u64 t; cvta.to.shared.u64 t, %1; cvt.u32.u64 %0, t; }" : "=r"(a) : "l"(p));
    return a;
}
__device__ __forceinline__ void cp16(uint32_t dst, const void* src) {
    asm volatile("cp.async.cg.shared.global [%0], [%1], 16;" :: "r"(dst), "l"(src));
}
#define CP_COMMIT() asm volatile("cp.async.commit_group;")
#define CP_WAIT(n)  asm volatile("cp.async.wait_group %0;" :: "n"(n))

#define MMA_BF16(acc, a, b0, b1) asm volatile( \
    "mma.sync.aligned.m16n8k16.row.col.f32.bf16.bf16.f32 " \
    "{%0,%1,%2,%3}, {%4,%5,%6,%7}, {%8,%9}, {%0,%1,%2,%3};" \
    : "+f"((acc)[0]), "+f"((acc)[1]), "+f"((acc)[2]), "+f"((acc)[3]) \
    : "r"((a)[0]), "r"((a)[1]), "r"((a)[2]), "r"((a)[3]), "r"(b0), "r"(b1))

#define LDMX4(r, addr) asm volatile( \
    "ldmatrix.sync.aligned.m8n8.x4.shared.b16 {%0,%1,%2,%3}, [%4];" \
    : "=r"((r)[0]), "=r"((r)[1]), "=r"((r)[2]), "=r"((r)[3]) : "r"(addr))

// ---------------------------------------------------------------------------
// Prep 1: x fp32 [M][C] -> g_x2 bf16 [M][3C] = [hi | hi | lo]
// ---------------------------------------------------------------------------
__global__ void split_expand_kernel(const float* __restrict__ src, int n4) {
    int i = blockIdx.x * blockDim.x + threadIdx.x;
    if (i >= n4) return;
    float4 v = ((const float4*)src)[i];
    float vv[4] = {v.x, v.y, v.z, v.w};
    int idx = i * 4;
    int m = idx / C_, k = idx % C_;
    size_t base = (size_t)m * K3_ + k;
#pragma unroll
    for (int j = 0; j < 4; j++) {
        __nv_bfloat16 hi = __float2bfloat16(vv[j]);
        __nv_bfloat16 lo = __float2bfloat16(vv[j] - __bfloat162float(hi));
        g_x2[base + j]          = hi;
        g_x2[base + C_ + j]     = hi;
        g_x2[base + 2*C_ + j]   = lo;
    }
}

// ---------------------------------------------------------------------------
// Prep 2: W fp32 [K][N] -> Wt bf16 [N][3K] = [hi | lo | hi]
// ---------------------------------------------------------------------------
template<int WHICH>
__global__ void transpose_split_expand_kernel(const float* __restrict__ W) {
    const int K = C_;
    const int N = (WHICH == 0) ? NQKV_ : C_;
    __nv_bfloat16* Bt = (WHICH == 0) ? g_w2q : g_w2o;

    __shared__ float tile[32][33];
    const int c0 = blockIdx.x * 32;
    const int r0 = blockIdx.y * 32;
    const int tx = threadIdx.x, ty = threadIdx.y;
#pragma unroll
    for (int i = 0; i < 4; i++)
        tile[ty + i*8][tx] = W[(size_t)(r0 + ty + i*8) * N + c0 + tx];
    __syncthreads();
#pragma unroll
    for (int i = 0; i < 4; i++) {
        float v = tile[tx][ty + i*8];
        __nv_bfloat16 hi = __float2bfloat16(v);
        __nv_bfloat16 lo = __float2bfloat16(v - __bfloat162float(hi));
        int n = c0 + ty + i*8, k = r0 + tx;
        size_t base = (size_t)n * K3_;
        Bt[base + k]        = hi;
        Bt[base + K + k]    = lo;
        Bt[base + 2*K + k]  = hi;
    }
}

// ---------------------------------------------------------------------------
// HMMA GEMM: K-slab 64, 2-stage double buffer, ONE WAIT(0)+barrier per slab.
// Pattern: WAIT(0); sync; issue(ks+1); compute(ks%2).
// issue(ks+1) targets stage (ks+1)%2 whose iter-(ks-1) readers all passed sync.
// Pitch 144 (128B data + 16 pad) -> ldmatrix 8-row gathers conflict-free.
// smem: 2 stages x (A 128x144 + B 128x144) = 73728 B.
// ---------------------------------------------------------------------------
#define GPITCH 144
#define G_B_OFF (128*GPITCH)      // 18432
#define G_STG   (256*GPITCH)      // 36864
#define GEMM_SMEM (2*G_STG)       // 73728

template<int MODE>
__global__ __launch_bounds__(256) void mma_gemm_kernel(float* __restrict__ outp)
{
    const __nv_bfloat16* __restrict__ A2 = (MODE == 0) ? g_x2 : g_a2;
    const __nv_bfloat16* __restrict__ B2 = (MODE == 0) ? g_w2q : g_w2o;

    extern __shared__ unsigned char smem[];
    const uint32_t sbase = smem_u32(smem);

    const int tid = threadIdx.x;
    const int wid = tid >> 5, lane = tid & 31;
    const int gid = lane >> 2, tig = lane & 3;
    const int m0 = blockIdx.y << 7, n0 = blockIdx.x << 7;
    const int warp_m = wid & 1, warp_n = wid >> 1;

    float acc[4][4][4];
#pragma unroll
    for (int a = 0; a < 4; a++)
#pragma unroll
        for (int b = 0; b < 4; b++)
#pragma unroll
            for (int c = 0; c < 4; c++) acc[a][b][c] = 0.f;

    // cooperative loads: per matrix 128 rows x 8 chunks(16B) = 1024 chunks,
    // 4 per thread; same for B.
    auto issue = [&](int ks) {
        const uint32_t st = sbase + (uint32_t)(ks & 1) * G_STG;
        const size_t ko = (size_t)ks * KS2;
#pragma unroll
        for (int i = 0; i < 4; i++) {
            const int c = tid + i*256;
            const int row = c >> 3, q = c & 7;
            cp16(st + row*GPITCH + q*16,           A2 + (size_t)(m0 + row)*K3_ + ko + q*8);
            cp16(st + G_B_OFF + row*GPITCH + q*16, B2 + (size_t)(n0 + row)*K3_ + ko + q*8);
        }
        CP_COMMIT();
    };

    issue(0);

    const int a_mrow = warp_m*64 + (lane & 7) + ((lane >> 3) & 1)*8;
    const uint32_t a_koff = (uint32_t)(lane >> 4) * 16;
    const int b_nrow = warp_n*32 + (lane & 7) + ((lane >> 4) & 1)*8;
    const uint32_t b_koff = (uint32_t)((lane >> 3) & 1) * 16;

    for (int ks = 0; ks < NSLAB2; ks++) {
        CP_WAIT(0);          // stage ks complete
        __syncthreads();     // visible; all warps done with stage (ks-1)
        if (ks + 1 < NSLAB2) issue(ks + 1);   // overlaps compute below

        const uint32_t bufA = sbase + (uint32_t)(ks & 1) * G_STG;
        const uint32_t bufB = bufA + G_B_OFF;

#pragma unroll
        for (int kst = 0; kst < 4; kst++) {
            uint32_t af[4][4];
#pragma unroll
            for (int tm = 0; tm < 4; tm++)
                LDMX4(af[tm], bufA + (a_mrow + tm*16)*GPITCH + kst*32 + a_koff);
            uint32_t bfr[2][4];
#pragma unroll
            for (int tp = 0; tp < 2; tp++)
                LDMX4(bfr[tp], bufB + (b_nrow + tp*16)*GPITCH + kst*32 + b_koff);
#pragma unroll
            for (int tm = 0; tm < 4; tm++)
#pragma unroll
                for (int tn = 0; tn < 4; tn++)
                    MMA_BF16(acc[tm][tn], af[tm],
                             bfr[tn>>1][(tn&1)*2], bfr[tn>>1][(tn&1)*2 + 1]);
        }
    }

    // ---- epilogue ----
#pragma unroll
    for (int tm = 0; tm < 4; tm++) {
        const int r0_ = m0 + warp_m*64 + tm*16 + gid;
#pragma unroll
        for (int tn = 0; tn < 4; tn++) {
            const int col = n0 + warp_n*32 + tn*8 + tig*2;
            if (MODE == 1) {
                float2 v0 = {acc[tm][tn][0], acc[tm][tn][1]};
                float2 v1 = {acc[tm][tn][2], acc[tm][tn][3]};
                *(float2*)&outp[(size_t)r0_ * C_ + col]       = v0;
                *(float2*)&outp[(size_t)(r0_ + 8) * C_ + col] = v1;
            } else {
                const int seg = n0 / C_;
                const int nrel = col - seg * C_;
                const int hh = nrel >> 6, dd = nrel & 63;
#pragma unroll
                for (int half = 0; half < 2; half++) {
                    const int m = r0_ + half * 8;
                    const int bb = m >> 11, tt = m & (T_ - 1);
                    const int bhh = bb*H_ + hh;
                    float v0 = acc[tm][tn][half*2], v1 = acc[tm][tn][half*2 + 1];
                    __nv_bfloat16 h0 = __float2bfloat16(v0);
                    __nv_bfloat16 h1 = __float2bfloat16(v1);
                    __nv_bfloat16 l0 = __float2bfloat16(v0 - __bfloat162float(h0));
                    __nv_bfloat16 l1 = __float2bfloat16(v1 - __bfloat162float(h1));
                    if (seg == 0) {
                        size_t base = ((size_t)bhh*T_ + tt)*D_ + dd;
                        *(uint32_t*)&g_qh[base] = pack_bf(h0, h1);
                        *(uint32_t*)&g_ql[base] = pack_bf(l0, l1);
                    } else if (seg == 1) {
                        size_t base = ((size_t)bhh*T_ + tt)*D_ + dd;
                        *(uint32_t*)&g_kh[base] = pack_bf(h0, h1);
                        *(uint32_t*)&g_kl[base] = pack_bf(l0, l1);
                    } else {
                        size_t base = ((size_t)bhh*D_ + dd)*T_ + tt;  // d-major
                        g_vh[base]      = h0;  g_vl[base]      = l0;
                        g_vh[base + T_] = h1;  g_vl[base + T_] = l1;
                    }
                }
            }
        }
    }
}

// ---------------------------------------------------------------------------
// HMMA causal flash attention: Q tile 128 rows, 8 warps (256 thr); per-warp
// body identical to the R11-R13 passing kernel (warp owns 16 q-rows).
// 2-stage cp.async K/V, ONE WAIT(0)+barrier per k-tile.  Diagonal spans two
// k-tiles (kt >= 2*qt -> generic mask).  smem:
//   Q hi @0, Q lo @18432 (128x144); KV stage s @36864 + s*36864:
//     KH +0, KL +9216, VH +18432, VL +27648.     Total 110592 B.
// ---------------------------------------------------------------------------
#define APITCH 144
#define AQ_LO  (128*APITCH)        // 18432
#define AKV_OFF (2*128*APITCH)     // 36864
#define AKV_STG 36864
#define ATTN_SMEM (AKV_OFF + 2*AKV_STG)   // 110592

__global__ __launch_bounds__(256) void attn_mma_kernel() {
    extern __shared__ unsigned char smem[];
    const uint32_t sbase = smem_u32(smem);
    const int tid = threadIdx.x;
    const int wid = tid >> 5, lane = tid & 31;
    const int gid = lane >> 2, tig = lane & 3;
    const int bh = blockIdx.y;
    const int b = bh / H_, h = bh % H_;
    const int qt = (int)(gridDim.x - 1) - (int)blockIdx.x;   // 0..15, heavy first
    const int ktmax = 2*qt + 1;

    const size_t qkbase = (size_t)bh * T_ * D_;
    const size_t vbase  = (size_t)bh * D_ * T_;

    // K/V slab loader: 4 matrices x 64 rows x 8 chunks = 2048 chunks / 256 thr
    auto issue_kv = [&](int kt2) {
        const uint32_t st = sbase + AKV_OFF + (uint32_t)(kt2 & 1) * AKV_STG;
#pragma unroll
        for (int i = 0; i < 2; i++) {
            const int c = tid + i*256;
            const int row = c >> 3, q = c & 7;
            const size_t gk = qkbase + (size_t)(kt2*64 + row)*D_ + q*8;
            const size_t gv = vbase + (size_t)row*T_ + kt2*64 + q*8;
            cp16(st +         row*APITCH + q*16, g_kh + gk);
            cp16(st + 9216  + row*APITCH + q*16, g_kl + gk);
            cp16(st + 18432 + row*APITCH + q*16, g_vh + gv);
            cp16(st + 27648 + row*APITCH + q*16, g_vl + gv);
        }
        CP_COMMIT();
    };

    // Load Q tile (128 rows hi/lo), plain stores; first loop barrier publishes
#pragma unroll
    for (int i = 0; i < 4; i++) {
        const int c = tid + i*256;
        const int row = c >> 3, q = c & 7;
        const size_t g = qkbase + (size_t)(qt*128 + row)*D_ + q*8;
        *(uint4*)(smem + row*APITCH + q*16)         = *(const uint4*)(g_qh + g);
        *(uint4*)(smem + AQ_LO + row*APITCH + q*16) = *(const uint4*)(g_ql + g);
    }

    issue_kv(0);

    float m0 = -1e30f, m1 = -1e30f, l0 = 0.f, l1 = 0.f;
    float o[8][4];
#pragma unroll
    for (int d = 0; d < 8; d++)
#pragma unroll
        for (int c = 0; c < 4; c++) o[d][c] = 0.f;

    const int arow = wid*16 + gid;          // 0..127
    const int grow0 = qt*128 + arow;

    for (int kt = 0; kt <= ktmax; kt++) {
        CP_WAIT(0);                          // stage kt arrived
        __syncthreads();                     // visible; stage kt-1 readers done
        if (kt + 1 <= ktmax) issue_kv(kt + 1);

        const unsigned char* kv = smem + AKV_OFF + (size_t)(kt & 1) * AKV_STG;
        const unsigned char* KH = kv;
        const unsigned char* KL = kv + 9216;
        const unsigned char* VH = kv + 18432;
        const unsigned char* VL = kv + 27648;

        float s[8][4];
#pragma unroll
        for (int nb = 0; nb < 8; nb++)
#pragma unroll
            for (int c = 0; c < 4; c++) s[nb][c] = 0.f;

#pragma unroll
        for (int kc = 0; kc < 4; kc++) {
            uint32_t ah[4], al[4];
            {
                const unsigned char* pa = smem + arow*APITCH + kc*32 + tig*4;
                ah[0] = *(const uint32_t*)(pa);
                ah[1] = *(const uint32_t*)(pa + 8*APITCH);
                ah[2] = *(const uint32_t*)(pa + 16);
                ah[3] = *(const uint32_t*)(pa + 8*APITCH + 16);
                const unsigned char* pl = smem + AQ_LO + arow*APITCH + kc*32 + tig*4;
                al[0] = *(const uint32_t*)(pl);
                al[1] = *(const uint32_t*)(pl + 8*APITCH);
                al[2] = *(const uint32_t*)(pl + 16);
                al[3] = *(const uint32_t*)(pl + 8*APITCH + 16);
            }
#pragma unroll
            for (int nb = 0; nb < 8; nb++) {
                const int n = nb*8 + gid;
                const unsigned char* pbh = KH + n*APITCH + kc*32 + tig*4;
                const unsigned char* pbl = KL + n*APITCH + kc*32 + tig*4;
                uint32_t bh0 = *(const uint32_t*)(pbh);
                uint32_t bh1 = *(const uint32_t*)(pbh + 16);
                uint32_t bl0 = *(const uint32_t*)(pbl);
                uint32_t bl1 = *(const uint32_t*)(pbl + 16);
                MMA_BF16(s[nb], ah, bh0, bh1);
                MMA_BF16(s[nb], ah, bl0, bl1);
                MMA_BF16(s[nb], al, bh0, bh1);
            }
        }

        const float scale = 0.125f;
        if (kt >= 2*qt) {                    // diagonal (two k-tiles)
#pragma unroll
            for (int nb = 0; nb < 8; nb++) {
                const int colb = kt*64 + nb*8 + tig*2;
                s[nb][0] = (colb     <= grow0    ) ? s[nb][0]*scale : -1e30f;
                s[nb][1] = (colb + 1 <= grow0    ) ? s[nb][1]*scale : -1e30f;
                s[nb][2] = (colb     <= grow0 + 8) ? s[nb][2]*scale : -1e30f;
                s[nb][3] = (colb + 1 <= grow0 + 8) ? s[nb][3]*scale : -1e30f;
            }
        } else {
#pragma unroll
            for (int nb = 0; nb < 8; nb++)
#pragma unroll
                for (int c = 0; c < 4; c++) s[nb][c] *= scale;
        }

        float mx0 = -1e30f, mx1 = -1e30f;
#pragma unroll
        for (int nb = 0; nb < 8; nb++) {
            mx0 = fmaxf(mx0, fmaxf(s[nb][0], s[nb][1]));
            mx1 = fmaxf(mx1, fmaxf(s[nb][2], s[nb][3]));
        }
#pragma unroll
        for (int off = 1; off <= 2; off <<= 1) {
            mx0 = fmaxf(mx0, __shfl_xor_sync(0xffffffffu, mx0, off));
            mx1 = fmaxf(mx1, __shfl_xor_sync(0xffffffffu, mx1, off));
        }
        const float mn0 = fmaxf(m0, mx0), mn1 = fmaxf(m1, mx1);
        const float cr0 = __expf(m0 - mn0), cr1 = __expf(m1 - mn1);
        float sum0 = 0.f, sum1 = 0.f;
#pragma unroll
        for (int nb = 0; nb < 8; nb++) {
            s[nb][0] = __expf(s[nb][0] - mn0);
            s[nb][1] = __expf(s[nb][1] - mn0);
            s[nb][2] = __expf(s[nb][2] - mn1);
            s[nb][3] = __expf(s[nb][3] - mn1);
            sum0 += s[nb][0] + s[nb][1];
            sum1 += s[nb][2] + s[nb][3];
        }
#pragma unroll
        for (int off = 1; off <= 2; off <<= 1) {
            sum0 += __shfl_xor_sync(0xffffffffu, sum0, off);
            sum1 += __shfl_xor_sync(0xffffffffu, sum1, off);
        }
        l0 = l0 * cr0 + sum0;  m0 = mn0;
        l1 = l1 * cr1 + sum1;  m1 = mn1;
#pragma unroll
        for (int db = 0; db < 8; db++) {
            o[db][0] *= cr0; o[db][1] *= cr0;
            o[db][2] *= cr1; o[db][3] *= cr1;
        }

        uint32_t ph[4][4], pl[4][4];
#pragma unroll
        for (int kc = 0; kc < 4; kc++) {
#pragma unroll
            for (int part = 0; part < 2; part++) {
                const int nb = 2*kc + part;
                __nv_bfloat16 h0 = __float2bfloat16(s[nb][0]);
                __nv_bfloat16 h1 = __float2bfloat16(s[nb][1]);
                __nv_bfloat16 h2 = __float2bfloat16(s[nb][2]);
                __nv_bfloat16 h3 = __float2bfloat16(s[nb][3]);
                ph[kc][0 + part*2] = pack_bf(h0, h1);
                ph[kc][1 + part*2] = pack_bf(h2, h3);
                pl[kc][0 + part*2] = pack_bf(
                    __float2bfloat16(s[nb][0] - __bfloat162float(h0)),
                    __float2bfloat16(s[nb][1] - __bfloat162float(h1)));
                pl[kc][1 + part*2] = pack_bf(
                    __float2bfloat16(s[nb][2] - __bfloat162float(h2)),
                    __float2bfloat16(s[nb][3] - __bfloat162float(h3)));
            }
        }

#pragma unroll
        for (int kc = 0; kc < 4; kc++) {
#pragma unroll
            for (int db = 0; db < 8; db++) {
                const int n = db*8 + gid;
                const unsigned char* pbh = VH + n*APITCH + kc*32 + tig*4;
                const unsigned char* pbl = VL + n*APITCH + kc*32 + tig*4;
                uint32_t bh0 = *(const uint32_t*)(pbh);
                uint32_t bh1 = *(const uint32_t*)(pbh + 16);
                uint32_t bl0 = *(const uint32_t*)(pbl);
                uint32_t bl1 = *(const uint32_t*)(pbl + 16);
                MMA_BF16(o[db], ph[kc], bh0, bh1);
                MMA_BF16(o[db], ph[kc], bl0, bl1);
                MMA_BF16(o[db], pl[kc], bh0, bh1);
            }
        }
    }

    const float i0 = 1.f / l0, i1 = 1.f / l1;
    const int gr = b*T_ + grow0;
#pragma unroll
    for (int db = 0; db < 8; db++) {
#pragma unroll
        for (int c = 0; c < 4; c++) {
            const float val = o[db][c] * ((c < 2) ? i0 : i1);
            const int row = (c < 2) ? gr : gr + 8;
            const int col = h*64 + db*8 + tig*2 + (c & 1);
            const size_t base = (size_t)row * K3_ + col;
            __nv_bfloat16 hi = __float2bfloat16(val);
            __nv_bfloat16 lo = __float2bfloat16(val - __bfloat162float(hi));
            g_a2[base]        = hi;
            g_a2[base + C_]   = hi;
            g_a2[base + 2*C_] = lo;
        }
    }
}

// ---------------------------------------------------------------------------
extern "C" void kernel_launch(void* const* d_in, const int* in_sizes, int n_in,
                              void* d_out, int out_size) {
    const float* x    = (const float*)d_in[0];
    const float* Wqkv = (const float*)d_in[1];
    const float* Wout = (const float*)d_in[2];
    float* out = (float*)d_out;

    split_expand_kernel<<<(M_*C_/4 + 255)/256, 256>>>(x, M_*C_/4);
    transpose_split_expand_kernel<0><<<dim3(NQKV_/32, C_/32), dim3(32, 8)>>>(Wqkv);
    transpose_split_expand_kernel<1><<<dim3(C_/32, C_/32), dim3(32, 8)>>>(Wout);

    // QKV projection (HMMA, K-slab 64, 2-stage, 1 barrier/slab)
    cudaFuncSetAttribute(mma_gemm_kernel<0>, cudaFuncAttributeMaxDynamicSharedMemorySize,
                         GEMM_SMEM);
    mma_gemm_kernel<0><<<dim3(NQKV_/128, M_/128), 256, GEMM_SMEM>>>(nullptr);

    // Flash attention on tensor cores (128-row Q tiles, 8 warps)
    cudaFuncSetAttribute(attn_mma_kernel, cudaFuncAttributeMaxDynamicSharedMemorySize,
                         ATTN_SMEM);
    attn_mma_kernel<<<dim3(T_/128, B_*H_), 256, ATTN_SMEM>>>();

    // Output projection (HMMA)
    cudaFuncSetAttribute(mma_gemm_kernel<1>, cudaFuncAttributeMaxDynamicSharedMemorySize,
                         GEMM_SMEM);
    mma_gemm_kernel<1><<<dim3(C_/128, M_/128), 256, GEMM_SMEM>>>(out);
}